// round 10
// baseline (speedup 1.0000x reference)
#include <cuda_runtime.h>
#include <cuda_bf16.h>
#include <math.h>
#include <stdint.h>

#define Bsz 512
#define HH 84
#define WW 84
#define KOBJ 20
#define DEPTH 24
#define EMB 512

// ---------------- scratch (static device globals; no allocations) ----------------
__device__ float g_h1[Bsz * 32 * 20 * 20];
__device__ float g_h2[Bsz * 64 * 9 * 9];
__device__ float g_h3[Bsz * 64 * 7 * 7];
__device__ float g_fcpart[7 * Bsz * EMB];
__device__ float g_x [Bsz * EMB];
__device__ float g_ot[Bsz * KOBJ * 2];
__device__ float g_ct[Bsz * 2];
__device__ float g_m21 [Bsz * DEPTH * 21 * 21];
__device__ float g_m42b[Bsz * DEPTH * 42 * 42];
__device__ float g_m84b[Bsz * DEPTH * 84 * 84];
__device__ uint32_t g_bfr42[6912];
__device__ uint32_t g_bfr84[6912];

// ---------------- helpers ----------------
__device__ __forceinline__ uint32_t pack_bf16x2(float lo, float hi) {
    uint32_t r;
    asm("cvt.rn.bf16x2.f32 %0, %1, %2;" : "=r"(r) : "f"(hi), "f"(lo));
    return r;  // low16 = bf16(lo), high16 = bf16(hi)
}
__device__ __forceinline__ void unpack_bf16x2(uint32_t u, float& lo, float& hi) {
    lo = __uint_as_float(u << 16);
    hi = __uint_as_float(u & 0xFFFF0000u);
}
__device__ __forceinline__ float bf16f(float v) {
    return __bfloat162float(__float2bfloat16(v));
}
__device__ __forceinline__ void mma_bf16(float c[4], const uint32_t a[4],
                                         uint32_t b0, uint32_t b1) {
    asm volatile("mma.sync.aligned.m16n8k16.row.col.f32.bf16.bf16.f32 "
        "{%0,%1,%2,%3}, {%4,%5,%6,%7}, {%8,%9}, {%0,%1,%2,%3};"
        : "+f"(c[0]), "+f"(c[1]), "+f"(c[2]), "+f"(c[3])
        : "r"(a[0]), "r"(a[1]), "r"(a[2]), "r"(a[3]), "r"(b0), "r"(b1));
}

// ---------------- B-fragment prep (once; layout identical to verified R9) ----------
__global__ __launch_bounds__(256) void k_bprep(const float* __restrict__ w42,
                                               const float* __restrict__ w84) {
    const float* w = blockIdx.x ? w84 : w42;
    uint32_t* dst = blockIdx.x ? g_bfr84 : g_bfr42;
    for (int e = threadIdx.x; e < 6912; e += 256) {
        int tap = e / 768;
        int rm = e % 768;
        int ks = rm / 384; rm %= 384;
        int hl = rm / 192; rm %= 192;
        int nt = rm / 64;
        int l2 = rm % 64;
        int ln = l2 >> 1, r = l2 & 1;
        int g = ln >> 2, tg = ln & 3;
        int oc = nt * 8 + g;
        int ic0 = ks * 16 + 2 * tg + r * 8;
        float v0 = 0.f, v1 = 0.f;
        if (ic0 < 24) {
            float wv = w[(oc * 24 + ic0) * 9 + tap];
            float h = bf16f(wv);
            v0 = (hl == 0) ? h : (wv - h);
        }
        if (ic0 + 1 < 24) {
            float wv = w[(oc * 24 + ic0 + 1) * 9 + tap];
            float h = bf16f(wv);
            v1 = (hl == 0) ? h : (wv - h);
        }
        dst[e] = pack_bf16x2(v0, v1);
    }
}

// ---------------- conv1: [B,2,84,84] k8 s4 -> [B,32,20,20], relu (512 thr) --------
__global__ __launch_bounds__(512) void k_conv1(const float* __restrict__ inp,
                                               const float* __restrict__ w,
                                               const float* __restrict__ bias) {
    extern __shared__ float sm[];
    float* sIn = sm;          // 14112
    float* sW  = sm + 14112;  // 4096
    int b = blockIdx.x, tid = threadIdx.x;
    const float* ip = inp + b * 14112;
    for (int i = tid; i < 14112; i += 512) sIn[i] = ip[i];
    for (int i = tid; i < 4096;  i += 512) sW[i]  = w[i];
    __syncthreads();
    for (int o = tid; o < 3200; o += 512) {
        int oc = o / 100; int r = o % 100;
        int oy = (r / 10) * 2, ox = (r % 10) * 2;
        float a00 = 0.f, a01 = 0.f, a10 = 0.f, a11 = 0.f;
        for (int ic = 0; ic < 2; ic++) {
            const float* wp  = sW + (oc * 2 + ic) * 64;
            const float* inb = sIn + ic * 7056;
            #pragma unroll
            for (int ky = 0; ky < 8; ky++) {
                const float* r0 = inb + (oy * 4 + ky) * 84 + ox * 4;
                const float* r1 = r0 + 4 * 84;
                float v0[12], v1[12];
                #pragma unroll
                for (int j = 0; j < 12; j++) { v0[j] = r0[j]; v1[j] = r1[j]; }
                #pragma unroll
                for (int kx = 0; kx < 8; kx++) {
                    float ww = wp[ky * 8 + kx];
                    a00 += v0[kx] * ww;  a01 += v0[kx + 4] * ww;
                    a10 += v1[kx] * ww;  a11 += v1[kx + 4] * ww;
                }
            }
        }
        float bb = bias[oc];
        float* op = g_h1 + b * 12800 + oc * 400 + oy * 20 + ox;
        op[0]  = fmaxf(a00 + bb, 0.f); op[1]  = fmaxf(a01 + bb, 0.f);
        op[20] = fmaxf(a10 + bb, 0.f); op[21] = fmaxf(a11 + bb, 0.f);
    }
}

// ---------------- conv2: [B,32,20,20] k4 s2 -> [B,64,9,9], relu (512 thr, 4 chunks)
__global__ __launch_bounds__(512) void k_conv2(const float* __restrict__ w,
                                               const float* __restrict__ bias) {
    extern __shared__ float sm[];
    float* sIn = sm;          // 12800
    float* sW  = sm + 12800;  // 8192 = 16 oc
    int b = blockIdx.x, tid = threadIdx.x;
    const float* ip = g_h1 + b * 12800;
    for (int i = tid; i < 12800; i += 512) sIn[i] = ip[i];
    for (int ch = 0; ch < 4; ch++) {
        __syncthreads();
        for (int i = tid; i < 8192; i += 512) sW[i] = w[ch * 8192 + i];
        __syncthreads();
        if (tid < 432) {
            int ocl = tid / 27; int r = tid % 27; int oy = r / 3; int oxg = (r % 3) * 3;
            float acc0 = 0.f, acc1 = 0.f, acc2 = 0.f;
            int iy0 = oy * 2, ix0 = oxg * 2;
            for (int ic = 0; ic < 32; ic++) {
                const float* wp0 = sW + (ocl * 32 + ic) * 16;
                #pragma unroll
                for (int ky = 0; ky < 4; ky++) {
                    const float* rp = sIn + ic * 400 + (iy0 + ky) * 20 + ix0;
                    float v[8];
                    #pragma unroll
                    for (int j = 0; j < 8; j++) v[j] = rp[j];
                    const float* wp = wp0 + ky * 4;
                    #pragma unroll
                    for (int kx = 0; kx < 4; kx++) {
                        float ww = wp[kx];
                        acc0 += v[kx] * ww;
                        acc1 += v[kx + 2] * ww;
                        acc2 += v[kx + 4] * ww;
                    }
                }
            }
            int oc = ch * 16 + ocl;
            float bb = bias[oc];
            float* op = g_h2 + b * 5184 + oc * 81 + oy * 9 + oxg;
            op[0] = fmaxf(acc0 + bb, 0.f);
            op[1] = fmaxf(acc1 + bb, 0.f);
            op[2] = fmaxf(acc2 + bb, 0.f);
        }
    }
}

// ---------------- conv3: [B,64,9,9] k3 s1 -> [B,64,7,7], relu (w3 via L2) --------
__global__ __launch_bounds__(256) void k_conv3(const float* __restrict__ w,
                                               const float* __restrict__ bias) {
    __shared__ float sH[5184];
    int b = blockIdx.x, tid = threadIdx.x;
    const float* ip = g_h2 + b * 5184;
    for (int i = tid; i < 5184; i += 256) sH[i] = ip[i];
    __syncthreads();
    for (int it = tid; it < 448; it += 256) {
        int oc = it / 7, oy = it % 7;
        float acc[7] = {};
        for (int ic = 0; ic < 64; ic++) {
            const float* wp = w + (oc * 64 + ic) * 9;
            float wr[9];
            #pragma unroll
            for (int q = 0; q < 9; q++) wr[q] = __ldg(wp + q);
            #pragma unroll
            for (int ky = 0; ky < 3; ky++) {
                const float* rp = sH + ic * 81 + (oy + ky) * 9;
                float v[9];
                #pragma unroll
                for (int j = 0; j < 9; j++) v[j] = rp[j];
                #pragma unroll
                for (int kx = 0; kx < 3; kx++) {
                    float ww = wr[ky * 3 + kx];
                    #pragma unroll
                    for (int j = 0; j < 7; j++) acc[j] += v[j + kx] * ww;
                }
            }
        }
        float bb = bias[oc];
        float* op = g_h3 + b * 3136 + oc * 49 + oy * 7;
        #pragma unroll
        for (int j = 0; j < 7; j++) op[j] = fmaxf(acc[j] + bb, 0.f);
    }
}

// ---------------- GEMM v2 ----------------
#define GBM 128
#define GBN 64
#define GBK 16
__global__ __launch_bounds__(256) void k_gemm2(const float* __restrict__ A,
                                               const float* __restrict__ W,
                                               const float* __restrict__ bias,
                                               float* __restrict__ C,
                                               int M, int N, int K, int Kc, int relu) {
    __shared__ float As[GBK][GBM];
    __shared__ float Ws[GBK][GBN];
    int bm = blockIdx.y * GBM, bn = blockIdx.x * GBN;
    int ks = blockIdx.z * Kc;
    int ke = min(ks + Kc, K);
    int tid = threadIdx.x;
    float acc[8][4];
    #pragma unroll
    for (int i = 0; i < 8; i++)
        #pragma unroll
        for (int j = 0; j < 4; j++) acc[i][j] = 0.f;

    int tm = (tid / 16) * 8, tn = (tid % 16) * 4;

    for (int k0 = ks; k0 < ke; k0 += GBK) {
        #pragma unroll
        for (int l = tid; l < 512; l += 256) {
            int m = l >> 2, kq = (l & 3) << 2;
            float4 v = *(const float4*)(A + (size_t)(bm + m) * K + k0 + kq);
            As[kq + 0][m] = v.x; As[kq + 1][m] = v.y;
            As[kq + 2][m] = v.z; As[kq + 3][m] = v.w;
        }
        {
            int n = tid >> 2, kq = (tid & 3) << 2;
            int gn = bn + n;
            float4 v = make_float4(0.f, 0.f, 0.f, 0.f);
            if (gn < N) v = *(const float4*)(W + (size_t)gn * K + k0 + kq);
            Ws[kq + 0][n] = v.x; Ws[kq + 1][n] = v.y;
            Ws[kq + 2][n] = v.z; Ws[kq + 3][n] = v.w;
        }
        __syncthreads();
        #pragma unroll
        for (int k = 0; k < GBK; k++) {
            float4 a0 = *(const float4*)&As[k][tm];
            float4 a1 = *(const float4*)&As[k][tm + 4];
            float4 bv = *(const float4*)&Ws[k][tn];
            float a[8] = {a0.x, a0.y, a0.z, a0.w, a1.x, a1.y, a1.z, a1.w};
            float bb[4] = {bv.x, bv.y, bv.z, bv.w};
            #pragma unroll
            for (int i = 0; i < 8; i++)
                #pragma unroll
                for (int j = 0; j < 4; j++) acc[i][j] += a[i] * bb[j];
        }
        __syncthreads();
    }

    if (Kc >= K) {
        #pragma unroll
        for (int i = 0; i < 8; i++) {
            int gm = bm + tm + i;
            #pragma unroll
            for (int j = 0; j < 4; j++) {
                int gn = bn + tn + j;
                if (gn < N) {
                    float v = acc[i][j] + bias[gn];
                    if (relu) v = fmaxf(v, 0.f);
                    C[(size_t)gm * N + gn] = v;
                }
            }
        }
    } else {
        float* Cp = C + (size_t)blockIdx.z * M * N;
        #pragma unroll
        for (int i = 0; i < 8; i++) {
            int gm = bm + tm + i;
            #pragma unroll
            for (int j = 0; j < 4; j++) {
                int gn = bn + tn + j;
                if (gn < N) Cp[(size_t)gm * N + gn] = acc[i][j];
            }
        }
    }
}

// ---------------- fc reduce + heads (warp-parallel heads) ----------------
__global__ __launch_bounds__(256) void k_fcredheads(const float* __restrict__ fcb,
                                                    const float* __restrict__ otw,
                                                    const float* __restrict__ otb,
                                                    const float* __restrict__ ctw,
                                                    const float* __restrict__ ctb) {
    __shared__ float sx[EMB];
    int b = blockIdx.x, tid = threadIdx.x;
    int lane = tid & 31, wid = tid >> 5;
    for (int i = tid; i < EMB; i += 256) {
        float s = fcb[i];
        #pragma unroll
        for (int p = 0; p < 7; p++) s += g_fcpart[p * Bsz * EMB + b * EMB + i];
        float v = fmaxf(s, 0.f);
        g_x[b * EMB + i] = v;
        sx[i] = v;
    }
    __syncthreads();
    #pragma unroll
    for (int j = 0; j < 6; j++) {
        int o = j * 8 + wid;
        if (o < 42) {
            const float* wp = (o < 40) ? (otw + o * EMB) : (ctw + (o - 40) * EMB);
            float s = 0.f;
            #pragma unroll
            for (int k = lane; k < EMB; k += 32) s += sx[k] * __ldg(wp + k);
            #pragma unroll
            for (int d = 16; d > 0; d >>= 1) s += __shfl_xor_sync(0xFFFFFFFFu, s, d);
            if (lane == 0) {
                if (o < 40) g_ot[b * 40 + o] = s + otb[o];
                else        g_ct[b * 2 + (o - 40)] = s + ctb[o - 40];
            }
        }
    }
}

// ======= fused upsample + residual 3x3 conv, bf16 m16n8k16 3-term, x-subtiled ======
// Band = 4 output rows; x-subtiles of 44 cols; tile [6][46][28] fp32; raw src rows
// staged [24][6][25]. B fragments read from precomputed global (L1-hot).
#define UWp 46
#define UW28 (UWp * 28)
#define UTILE (6 * UW28)        // 7728
#define URAWW 25
#define URAW (24 * 6 * URAWW)   // 3600
__global__ __launch_bounds__(256, 4) void k_upconv_hmma(
        const float* __restrict__ src, const float* __restrict__ bias,
        float* __restrict__ out, const uint32_t* __restrict__ bfrag,
        int inS, int S, float scale, int nsub) {
    extern __shared__ float sm[];
    float* sTile = sm;
    float* sRaw  = sm + UTILE;
    float* sBias = sm + UTILE + URAW;
    int tid = threadIdx.x, lane = tid & 31, wid = tid >> 5;
    int b = blockIdx.y, band = blockIdx.x;
    int y0 = band * 4;
    int g = lane >> 2, tg = lane & 3;
    if (tid < 24) sBias[tid] = bias[tid];
    const float* srcb = src + (size_t)b * 24 * inS * inS;
    float* ob = out + (size_t)b * 24 * S * S;
    int sy0 = (int)(fmaxf((float)(y0 - 1), 0.f) * scale);

    for (int s = 0; s < nsub; s++) {
        int x0 = s * 44;
        int npx = min(11, (S - x0 + 3) >> 2);
        int sx0 = (int)(fmaxf((float)(x0 - 1), 0.f) * scale);
        __syncthreads();
        // stage raw src rows (coalesced)
        for (int e = tid; e < URAW; e += 256) {
            int ic = e / (6 * URAWW);
            int r2 = e % (6 * URAWW);
            int ry = r2 / URAWW, xx = r2 % URAWW;
            int sy = sy0 + ry, sx = sx0 + xx;
            sRaw[e] = (sy < inS && sx < inS)
                    ? srcb[(size_t)ic * inS * inS + sy * inS + sx] : 0.f;
        }
        __syncthreads();
        // bilinear upsample -> fp32 tile (ic-last, pad 28, zero borders)
        for (int e = tid; e < UTILE; e += 256) {
            int ic = e % 28;
            int t = e / 28;
            int c = t % UWp, r = t / UWp;
            int gy = y0 + r - 1, gx = x0 + c - 1;
            float v = 0.f;
            if (ic < 24 && gy >= 0 && gy < S && gx >= 0 && gx < S) {
                float py = gy * scale;
                int yl = min((int)py, inS - 2);
                float wy = py - (float)yl;
                float px = gx * scale;
                int xl = min((int)px, inS - 2);
                float wx = px - (float)xl;
                const float* rp = sRaw + ic * (6 * URAWW) + (yl - sy0) * URAWW
                                + (xl - sx0);
                float v00 = rp[0], v01 = rp[1], v10 = rp[URAWW], v11 = rp[URAWW + 1];
                v = (1.f - wy) * ((1.f - wx) * v00 + wx * v01) +
                    wy * ((1.f - wx) * v10 + wx * v11);
            }
            sTile[e] = v;
        }
        __syncthreads();
        // per-warp patch loop
        for (int p = wid; p < npx; p += 8) {
            int colb = p * 4 + (g & 3);
            float c0[4] = {0.f, 0.f, 0.f, 0.f};
            float c1[4] = {0.f, 0.f, 0.f, 0.f};
            float c2[4] = {0.f, 0.f, 0.f, 0.f};
            #pragma unroll
            for (int ky = 0; ky < 3; ky++) {
                #pragma unroll
                for (int kx = 0; kx < 3; kx++) {
                    int tap = ky * 3 + kx;
                    int rb = ((g >> 2) + ky) * UW28 + (colb + kx) * 28;
                    #pragma unroll
                    for (int ks = 0; ks < 2; ks++) {
                        int ab = rb + ks * 16 + 2 * tg;
                        float2 p0 = *(const float2*)(sTile + ab);
                        float2 p1 = *(const float2*)(sTile + ab + 2 * UW28);
                        float2 p2 = *(const float2*)(sTile + ab + 8);
                        float2 p3 = *(const float2*)(sTile + ab + 2 * UW28 + 8);
                        uint32_t ah[4], al[4];
                        ah[0] = pack_bf16x2(p0.x, p0.y);
                        ah[1] = pack_bf16x2(p1.x, p1.y);
                        ah[2] = pack_bf16x2(p2.x, p2.y);
                        ah[3] = pack_bf16x2(p3.x, p3.y);
                        {
                            float h0, h1;
                            unpack_bf16x2(ah[0], h0, h1);
                            al[0] = pack_bf16x2(p0.x - h0, p0.y - h1);
                            unpack_bf16x2(ah[1], h0, h1);
                            al[1] = pack_bf16x2(p1.x - h0, p1.y - h1);
                            unpack_bf16x2(ah[2], h0, h1);
                            al[2] = pack_bf16x2(p2.x - h0, p2.y - h1);
                            unpack_bf16x2(ah[3], h0, h1);
                            al[3] = pack_bf16x2(p3.x - h0, p3.y - h1);
                        }
                        const uint2* bh = (const uint2*)(bfrag + (tap * 4 + ks * 2) * 192);
                        const uint2* bl = (const uint2*)(bfrag + (tap * 4 + ks * 2 + 1) * 192);
                        uint2 bh0 = __ldg(bh + lane);
                        uint2 bh1 = __ldg(bh + 32 + lane);
                        uint2 bh2 = __ldg(bh + 64 + lane);
                        uint2 bl0 = __ldg(bl + lane);
                        uint2 bl1 = __ldg(bl + 32 + lane);
                        uint2 bl2 = __ldg(bl + 64 + lane);
                        mma_bf16(c0, ah, bh0.x, bh0.y);
                        mma_bf16(c1, ah, bh1.x, bh1.y);
                        mma_bf16(c2, ah, bh2.x, bh2.y);
                        mma_bf16(c0, al, bh0.x, bh0.y);
                        mma_bf16(c1, al, bh1.x, bh1.y);
                        mma_bf16(c2, al, bh2.x, bh2.y);
                        mma_bf16(c0, ah, bl0.x, bl0.y);
                        mma_bf16(c1, ah, bl1.x, bl1.y);
                        mma_bf16(c2, ah, bl2.x, bl2.y);
                    }
                }
            }
            // epilogue: fp32 residual + bias + relu, masked stores
            int gx = x0 + colb;
            int pr = g >> 2;
            int gy0 = y0 + pr, gy1 = y0 + pr + 2;
            const float* rc0 = sTile + (pr + 1) * UW28 + (colb + 1) * 28;
            const float* rc1 = rc0 + 2 * UW28;
            bool v0 = (gy0 < S) && (gx < S);
            bool v1 = (gy1 < S) && (gx < S);
            #pragma unroll
            for (int nt = 0; nt < 3; nt++) {
                const float* cp = (nt == 0) ? c0 : (nt == 1) ? c1 : c2;
                int oc = nt * 8 + 2 * tg;
                if (v0) {
                    ob[((size_t)oc * S + gy0) * S + gx] =
                        fmaxf(cp[0] + rc0[oc] + sBias[oc], 0.f);
                    ob[((size_t)(oc + 1) * S + gy0) * S + gx] =
                        fmaxf(cp[1] + rc0[oc + 1] + sBias[oc + 1], 0.f);
                }
                if (v1) {
                    ob[((size_t)oc * S + gy1) * S + gx] =
                        fmaxf(cp[2] + rc1[oc] + sBias[oc], 0.f);
                    ob[((size_t)(oc + 1) * S + gy1) * S + gx] =
                        fmaxf(cp[3] + rc1[oc + 1] + sBias[oc + 1], 0.f);
                }
            }
        }
    }
}

// ---------------- fused epilogue: 1x1 conv + sigmoid + flow + ct + grid + warp --------
__global__ __launch_bounds__(256) void k_final(const float* __restrict__ inp,
                                               const float* __restrict__ c3w,
                                               const float* __restrict__ c3b,
                                               float* __restrict__ outp) {
    __shared__ float s_w[KOBJ * 24];
    __shared__ float s_b[KOBJ];
    __shared__ float s_ot[KOBJ * 2];
    __shared__ float s_ct[2];
    int b = blockIdx.y, tid = threadIdx.x;
    int p = blockIdx.x * 256 + tid;
    for (int i = tid; i < KOBJ * 24; i += 256) s_w[i] = c3w[i];
    if (tid < KOBJ) s_b[tid] = c3b[tid];
    if (tid < KOBJ * 2) s_ot[tid] = g_ot[b * 40 + tid];
    if (tid < 2) s_ct[tid] = g_ct[b * 2 + tid];
    __syncthreads();
    if (p >= 7056) return;
    const float* mp = g_m84b + (size_t)b * 24 * 7056 + p;
    float mv[24];
    #pragma unroll
    for (int c = 0; c < 24; c++) mv[c] = mp[c * 7056];
    float fy = s_ct[0], fx = s_ct[1];
    #pragma unroll 4
    for (int k = 0; k < KOBJ; k++) {
        float s = s_b[k];
        #pragma unroll
        for (int c = 0; c < 24; c++) s += mv[c] * s_w[k * 24 + c];
        float mask = 1.f / (1.f + __expf(-s));
        fy += mask * s_ot[k * 2];
        fx += mask * s_ot[k * 2 + 1];
    }
    int gy = p / 84, gx = p % 84;
    const float isf = 0.01f * 84.0f;
    float ys = isf * fy + (float)gy;
    float xs = isf * fx + (float)gx;
    const float* src = inp + (size_t)b * 14112 + 7056;
    int x0 = min(max((int)floorf(xs), 0), 83);
    int y0 = min(max((int)floorf(ys), 0), 83);
    int x1 = min(x0 + 1, 83);
    int y1 = min(y0 + 1, 83);
    float Ia = src[y0 * 84 + x0], Ib = src[y1 * 84 + x0];
    float Ic = src[y0 * 84 + x1], Id = src[y1 * 84 + x1];
    float xc = fminf(fmaxf(xs, 0.f), 83.f);
    float yc = fminf(fmaxf(ys, 0.f), 83.f);
    float x0f = (float)x0, x1f = (float)x1, y0f = (float)y0, y1f = (float)y1;
    float o = (x1f - xc) * (y1f - yc) * Ia + (x1f - xc) * (yc - y0f) * Ib +
              (xc - x0f) * (y1f - yc) * Ic + (xc - x0f) * (yc - y0f) * Id;
    outp[(size_t)b * 7056 + p] = o;
}

// ---------------- launch ----------------
extern "C" void kernel_launch(void* const* d_in, const int* in_sizes, int n_in,
                              void* d_out, int out_size) {
    const float* inp = (const float*)d_in[0];
    const float* cw1 = (const float*)d_in[1];
    const float* cb1 = (const float*)d_in[2];
    const float* cw2 = (const float*)d_in[3];
    const float* cb2 = (const float*)d_in[4];
    const float* cw3 = (const float*)d_in[5];
    const float* cb3 = (const float*)d_in[6];
    const float* fcw = (const float*)d_in[7];
    const float* fcb = (const float*)d_in[8];
    const float* otw = (const float*)d_in[9];
    const float* otb = (const float*)d_in[10];
    const float* ctw = (const float*)d_in[11];
    const float* ctb = (const float*)d_in[12];
    const float* m1w = (const float*)d_in[13];
    const float* m1b = (const float*)d_in[14];
    const float* c1w = (const float*)d_in[15];
    const float* c1b = (const float*)d_in[16];
    const float* c2w = (const float*)d_in[17];
    const float* c2b = (const float*)d_in[18];
    const float* c3w = (const float*)d_in[19];
    const float* c3b = (const float*)d_in[20];
    float* outp = (float*)d_out;

    cudaFuncSetAttribute(k_conv1, cudaFuncAttributeMaxDynamicSharedMemorySize, 72832);
    cudaFuncSetAttribute(k_conv2, cudaFuncAttributeMaxDynamicSharedMemorySize, 83968);

    float *p_h3, *p_x, *p_fcpart, *p_m21, *p_m42b, *p_m84b;
    uint32_t *p_bfr42, *p_bfr84;
    cudaGetSymbolAddress((void**)&p_h3,     g_h3);
    cudaGetSymbolAddress((void**)&p_x,      g_x);
    cudaGetSymbolAddress((void**)&p_fcpart, g_fcpart);
    cudaGetSymbolAddress((void**)&p_m21,    g_m21);
    cudaGetSymbolAddress((void**)&p_m42b,   g_m42b);
    cudaGetSymbolAddress((void**)&p_m84b,   g_m84b);
    cudaGetSymbolAddress((void**)&p_bfr42,  g_bfr42);
    cudaGetSymbolAddress((void**)&p_bfr84,  g_bfr84);

    // (1) weight fragments for the decoder — independent, runs first
    k_bprep<<<2, 256>>>(c1w, c2w);
    // encoder
    k_conv1<<<Bsz, 512, 72832>>>(inp, cw1, cb1);
    k_conv2<<<Bsz, 512, 83968>>>(cw2, cb2);
    k_conv3<<<Bsz, 256>>>(cw3, cb3);              // 4th launch -> profiled
    // fc: split-K=7 + fused reduce(relu)+heads
    k_gemm2<<<dim3(EMB / GBN, Bsz / GBM, 7), 256>>>(p_h3, fcw, fcb, p_fcpart,
                                                    Bsz, EMB, 3136, 448, 0);
    k_fcredheads<<<Bsz, 256>>>(fcb, otw, otb, ctw, ctb);
    // mask fc
    k_gemm2<<<dim3((10584 + GBN - 1) / GBN, Bsz / GBM, 1), 256>>>(p_x, m1w, m1b, p_m21,
                                                                  Bsz, 10584, EMB, EMB, 0);
    // decoder: smem = (7728 + 3600 + 24)*4 = 45408 B -> 4 blocks/SM
    k_upconv_hmma<<<dim3(11, Bsz), 256, 45408>>>(p_m21, c1b, p_m42b, p_bfr42,
                                                 21, 42, 20.f / 41.f, 1);
    k_upconv_hmma<<<dim3(21, Bsz), 256, 45408>>>(p_m42b, c2b, p_m84b, p_bfr84,
                                                 42, 84, 41.f / 83.f, 2);
    // fused: 1x1 conv + sigmoid masks + flow + warp
    k_final<<<dim3(28, Bsz), 256>>>(inp, c3w, c3b, outp);
    (void)in_sizes; (void)n_in; (void)out_size;
}

// round 11
// speedup vs baseline: 1.5611x; 1.5611x over previous
#include <cuda_runtime.h>
#include <cuda_bf16.h>
#include <math.h>
#include <stdint.h>

#define Bsz 512
#define HH 84
#define WW 84
#define KOBJ 20
#define DEPTH 24
#define EMB 512

// ---------------- scratch (static device globals; no allocations) ----------------
__device__ float g_h1[Bsz * 32 * 20 * 20];
__device__ float g_h3[Bsz * 64 * 7 * 7];
__device__ float g_fcpart[7 * Bsz * EMB];
__device__ float g_x [Bsz * EMB];
__device__ float g_ot[Bsz * KOBJ * 2];
__device__ float g_ct[Bsz * 2];
__device__ float g_m21 [Bsz * DEPTH * 21 * 21];
__device__ float g_m42b[Bsz * DEPTH * 42 * 42];
__device__ float g_m84b[Bsz * DEPTH * 84 * 84];

// ---------------- helpers ----------------
__device__ __forceinline__ uint32_t pack_bf16x2(float lo, float hi) {
    uint32_t r;
    asm("cvt.rn.bf16x2.f32 %0, %1, %2;" : "=r"(r) : "f"(hi), "f"(lo));
    return r;  // low16 = bf16(lo), high16 = bf16(hi)
}
__device__ __forceinline__ void unpack_bf16x2(uint32_t u, float& lo, float& hi) {
    lo = __uint_as_float(u << 16);
    hi = __uint_as_float(u & 0xFFFF0000u);
}
__device__ __forceinline__ float bf16f(float v) {
    return __bfloat162float(__float2bfloat16(v));
}
__device__ __forceinline__ void mma_bf16(float c[4], const uint32_t a[4],
                                         uint32_t b0, uint32_t b1) {
    asm volatile("mma.sync.aligned.m16n8k16.row.col.f32.bf16.bf16.f32 "
        "{%0,%1,%2,%3}, {%4,%5,%6,%7}, {%8,%9}, {%0,%1,%2,%3};"
        : "+f"(c[0]), "+f"(c[1]), "+f"(c[2]), "+f"(c[3])
        : "r"(a[0]), "r"(a[1]), "r"(a[2]), "r"(a[3]), "r"(b0), "r"(b1));
}

// ---------------- conv1: [B,2,84,84] k8 s4 -> [B,32,20,20], relu ----------------
__global__ __launch_bounds__(256) void k_conv1(const float* __restrict__ inp,
                                               const float* __restrict__ w,
                                               const float* __restrict__ bias) {
    extern __shared__ float sm[];
    float* sIn = sm;          // 14112
    float* sW  = sm + 14112;  // 4096
    int b = blockIdx.x, tid = threadIdx.x;
    const float* ip = inp + b * 14112;
    for (int i = tid; i < 14112; i += 256) sIn[i] = ip[i];
    for (int i = tid; i < 4096;  i += 256) sW[i]  = w[i];
    __syncthreads();
    for (int o = tid; o < 3200; o += 256) {
        int oc = o / 100; int r = o % 100;
        int oy = (r / 10) * 2, ox = (r % 10) * 2;
        float a00 = 0.f, a01 = 0.f, a10 = 0.f, a11 = 0.f;
        for (int ic = 0; ic < 2; ic++) {
            const float* wp  = sW + (oc * 2 + ic) * 64;
            const float* inb = sIn + ic * 7056;
            #pragma unroll
            for (int ky = 0; ky < 8; ky++) {
                const float* r0 = inb + (oy * 4 + ky) * 84 + ox * 4;
                const float* r1 = r0 + 4 * 84;
                float v0[12], v1[12];
                #pragma unroll
                for (int j = 0; j < 12; j++) { v0[j] = r0[j]; v1[j] = r1[j]; }
                #pragma unroll
                for (int kx = 0; kx < 8; kx++) {
                    float ww = wp[ky * 8 + kx];
                    a00 += v0[kx] * ww;  a01 += v0[kx + 4] * ww;
                    a10 += v1[kx] * ww;  a11 += v1[kx + 4] * ww;
                }
            }
        }
        float bb = bias[oc];
        float* op = g_h1 + b * 12800 + oc * 400 + oy * 20 + ox;
        op[0]  = fmaxf(a00 + bb, 0.f); op[1]  = fmaxf(a01 + bb, 0.f);
        op[20] = fmaxf(a10 + bb, 0.f); op[21] = fmaxf(a11 + bb, 0.f);
    }
}

// ---------------- conv2+conv3 fused (h2 stays in smem) ----------------
__global__ __launch_bounds__(256) void k_conv23(const float* __restrict__ w2,
                                                const float* __restrict__ b2,
                                                const float* __restrict__ w3,
                                                const float* __restrict__ b3) {
    extern __shared__ float sm[];
    float* sIn1 = sm;
    float* sW2  = sm + 12800;
    float* sH2  = sm + 36864;
    int b = blockIdx.x, tid = threadIdx.x;
    const float* ip = g_h1 + b * 12800;
    for (int i = tid; i < 12800; i += 256) sIn1[i] = ip[i];
    for (int ch = 0; ch < 2; ch++) {
        __syncthreads();
        for (int i = tid; i < 16384; i += 256) sW2[i] = w2[ch * 16384 + i];
        __syncthreads();
        if (tid < 216) {
            int ocg = tid / 27; int r = tid % 27; int oy = r / 3; int oxg = (r % 3) * 3;
            float acc[4][3] = {};
            int iy0 = oy * 2, ix0 = oxg * 2;
            for (int ic = 0; ic < 32; ic++) {
                #pragma unroll
                for (int ky = 0; ky < 4; ky++) {
                    const float* rp = sIn1 + ic * 400 + (iy0 + ky) * 20 + ix0;
                    float v[8];
                    #pragma unroll
                    for (int j = 0; j < 8; j++) v[j] = rp[j];
                    #pragma unroll
                    for (int u = 0; u < 4; u++) {
                        const float* wp = sW2 + ((ocg * 4 + u) * 32 + ic) * 16 + ky * 4;
                        #pragma unroll
                        for (int kx = 0; kx < 4; kx++) {
                            float ww = wp[kx];
                            acc[u][0] += v[kx] * ww;
                            acc[u][1] += v[kx + 2] * ww;
                            acc[u][2] += v[kx + 4] * ww;
                        }
                    }
                }
            }
            #pragma unroll
            for (int u = 0; u < 4; u++) {
                int oc = ch * 32 + ocg * 4 + u;
                float bb = b2[oc];
                float* op = sH2 + oc * 81 + oy * 9 + oxg;
                #pragma unroll
                for (int j = 0; j < 3; j++) op[j] = fmaxf(acc[u][j] + bb, 0.f);
            }
        }
    }
    __syncthreads();
    for (int i = tid; i < 36864; i += 256) sm[i] = w3[i];
    __syncthreads();
    for (int it = tid; it < 448; it += 256) {
        int oc = it / 7, oy = it % 7;
        float acc[7] = {};
        for (int ic = 0; ic < 64; ic++) {
            const float* wp = sm + (oc * 64 + ic) * 9;
            #pragma unroll
            for (int ky = 0; ky < 3; ky++) {
                const float* rp = sH2 + ic * 81 + (oy + ky) * 9;
                float v[9];
                #pragma unroll
                for (int j = 0; j < 9; j++) v[j] = rp[j];
                #pragma unroll
                for (int kx = 0; kx < 3; kx++) {
                    float ww = wp[ky * 3 + kx];
                    #pragma unroll
                    for (int j = 0; j < 7; j++) acc[j] += v[j + kx] * ww;
                }
            }
        }
        float bb = b3[oc];
        float* op = g_h3 + b * 3136 + oc * 49 + oy * 7;
        #pragma unroll
        for (int j = 0; j < 7; j++) op[j] = fmaxf(acc[j] + bb, 0.f);
    }
}

// ---------------- GEMM v2 ----------------
#define GBM 128
#define GBN 64
#define GBK 16
__global__ __launch_bounds__(256) void k_gemm2(const float* __restrict__ A,
                                               const float* __restrict__ W,
                                               const float* __restrict__ bias,
                                               float* __restrict__ C,
                                               int M, int N, int K, int Kc, int relu) {
    __shared__ float As[GBK][GBM];
    __shared__ float Ws[GBK][GBN];
    int bm = blockIdx.y * GBM, bn = blockIdx.x * GBN;
    int ks = blockIdx.z * Kc;
    int ke = min(ks + Kc, K);
    int tid = threadIdx.x;
    float acc[8][4];
    #pragma unroll
    for (int i = 0; i < 8; i++)
        #pragma unroll
        for (int j = 0; j < 4; j++) acc[i][j] = 0.f;

    int tm = (tid / 16) * 8, tn = (tid % 16) * 4;

    for (int k0 = ks; k0 < ke; k0 += GBK) {
        #pragma unroll
        for (int l = tid; l < 512; l += 256) {
            int m = l >> 2, kq = (l & 3) << 2;
            float4 v = *(const float4*)(A + (size_t)(bm + m) * K + k0 + kq);
            As[kq + 0][m] = v.x; As[kq + 1][m] = v.y;
            As[kq + 2][m] = v.z; As[kq + 3][m] = v.w;
        }
        {
            int n = tid >> 2, kq = (tid & 3) << 2;
            int gn = bn + n;
            float4 v = make_float4(0.f, 0.f, 0.f, 0.f);
            if (gn < N) v = *(const float4*)(W + (size_t)gn * K + k0 + kq);
            Ws[kq + 0][n] = v.x; Ws[kq + 1][n] = v.y;
            Ws[kq + 2][n] = v.z; Ws[kq + 3][n] = v.w;
        }
        __syncthreads();
        #pragma unroll
        for (int k = 0; k < GBK; k++) {
            float4 a0 = *(const float4*)&As[k][tm];
            float4 a1 = *(const float4*)&As[k][tm + 4];
            float4 bv = *(const float4*)&Ws[k][tn];
            float a[8] = {a0.x, a0.y, a0.z, a0.w, a1.x, a1.y, a1.z, a1.w};
            float bb[4] = {bv.x, bv.y, bv.z, bv.w};
            #pragma unroll
            for (int i = 0; i < 8; i++)
                #pragma unroll
                for (int j = 0; j < 4; j++) acc[i][j] += a[i] * bb[j];
        }
        __syncthreads();
    }

    if (Kc >= K) {
        #pragma unroll
        for (int i = 0; i < 8; i++) {
            int gm = bm + tm + i;
            #pragma unroll
            for (int j = 0; j < 4; j++) {
                int gn = bn + tn + j;
                if (gn < N) {
                    float v = acc[i][j] + bias[gn];
                    if (relu) v = fmaxf(v, 0.f);
                    C[(size_t)gm * N + gn] = v;
                }
            }
        }
    } else {
        float* Cp = C + (size_t)blockIdx.z * M * N;
        #pragma unroll
        for (int i = 0; i < 8; i++) {
            int gm = bm + tm + i;
            #pragma unroll
            for (int j = 0; j < 4; j++) {
                int gn = bn + tn + j;
                if (gn < N) Cp[(size_t)gm * N + gn] = acc[i][j];
            }
        }
    }
}

// ---------------- fc reduce + heads (warp-parallel heads) ----------------
__global__ __launch_bounds__(256) void k_fcredheads(const float* __restrict__ fcb,
                                                    const float* __restrict__ otw,
                                                    const float* __restrict__ otb,
                                                    const float* __restrict__ ctw,
                                                    const float* __restrict__ ctb) {
    __shared__ float sx[EMB];
    int b = blockIdx.x, tid = threadIdx.x;
    int lane = tid & 31, wid = tid >> 5;
    for (int i = tid; i < EMB; i += 256) {
        float s = fcb[i];
        #pragma unroll
        for (int p = 0; p < 7; p++) s += g_fcpart[p * Bsz * EMB + b * EMB + i];
        float v = fmaxf(s, 0.f);
        g_x[b * EMB + i] = v;
        sx[i] = v;
    }
    __syncthreads();
    #pragma unroll
    for (int j = 0; j < 6; j++) {
        int o = j * 8 + wid;
        if (o < 42) {
            const float* wp = (o < 40) ? (otw + o * EMB) : (ctw + (o - 40) * EMB);
            float s = 0.f;
            #pragma unroll
            for (int k = lane; k < EMB; k += 32) s += sx[k] * wp[k];
            #pragma unroll
            for (int d = 16; d > 0; d >>= 1) s += __shfl_xor_sync(0xFFFFFFFFu, s, d);
            if (lane == 0) {
                if (o < 40) g_ot[b * 40 + o] = s + otb[o];
                else        g_ct[b * 2 + (o - 40)] = s + ctb[o - 40];
            }
        }
    }
}

// ==== fused upsample + residual 3x3 conv, bf16 HMMA 3-term, hi/lo tiles in smem ====
// Band = 4 output rows, full width. Pixel record = 18 u32, slot-interleaved so each
// A-fragment pair (a0,a2) is ONE LDS.64: slots {0,2,4,6,1,3,5,7,8,10,12,14}, zeros
// at 9,11,13,15. smem: sHi[tileU], sLo[tileU], sAux (raw floats -> B frags 6912 u32),
// sBias[24].
__global__ __launch_bounds__(256, 2) void k_upconv_hmma2(
        const float* __restrict__ src, const float* __restrict__ w,
        const float* __restrict__ bias, float* __restrict__ out,
        int inS, int S, int Wp, int npx, float scale, int tileU) {
    extern __shared__ uint32_t smu[];
    uint32_t* sHi = smu;
    uint32_t* sLo = smu + tileU;
    uint32_t* sAux = smu + 2 * tileU;        // raw staging then B fragments
    float* sRawF = (float*)sAux;
    float* sBias = (float*)(sAux + 6912);
    int tid = threadIdx.x, lane = tid & 31, wid = tid >> 5;
    int b = blockIdx.y, band = blockIdx.x;
    int y0 = band * 4;
    int g = lane >> 2, tg = lane & 3;

    // phase 0: stage raw src rows [ic][6][inS] + bias
    int sy0 = (int)(fmaxf((float)(y0 - 1), 0.f) * scale);
    const float* srcb = src + (size_t)b * 24 * inS * inS;
    int rawTot = 24 * 6 * inS;
    for (int e = tid; e < rawTot; e += 256) {
        int ic = e / (6 * inS);
        int r2 = e % (6 * inS);
        int ry = r2 / inS, x = r2 % inS;
        int sy = sy0 + ry;
        sRawF[e] = (sy < inS) ? srcb[(size_t)ic * inS * inS + sy * inS + x] : 0.f;
    }
    if (tid < 24) sBias[tid] = bias[tid];
    __syncthreads();

    // phase 1: bilinear upsample -> bf16 hi/lo records
    for (int pix = tid; pix < 6 * Wp; pix += 256) {
        int r = pix / Wp, c = pix - r * Wp;
        int gy = y0 + r - 1, gx = c - 1;
        uint32_t* rh = sHi + pix * 18;
        uint32_t* rl = sLo + pix * 18;
        float vb[24];
        if (gy >= 0 && gy < S && gx >= 0 && gx < S) {
            float py = gy * scale;
            int yl = min((int)py, inS - 2);
            float wy = py - (float)yl;
            float px = gx * scale;
            int xl = min((int)px, inS - 2);
            float wx = px - (float)xl;
            const float* base = sRawF + (yl - sy0) * inS + xl;
            #pragma unroll
            for (int ic = 0; ic < 24; ic++) {
                const float* rp = base + ic * (6 * inS);
                float v00 = rp[0], v01 = rp[1], v10 = rp[inS], v11 = rp[inS + 1];
                vb[ic] = (1.f - wy) * ((1.f - wx) * v00 + wx * v01) +
                         wy * ((1.f - wx) * v10 + wx * v11);
            }
        } else {
            #pragma unroll
            for (int ic = 0; ic < 24; ic++) vb[ic] = 0.f;
        }
        const int slotA[12] = {0, 2, 4, 6, 1, 3, 5, 7, 8, 10, 12, 14};
        #pragma unroll
        for (int j = 0; j < 12; j++) {
            uint32_t h = pack_bf16x2(vb[2 * j], vb[2 * j + 1]);
            float h0, h1;
            unpack_bf16x2(h, h0, h1);
            uint32_t l = pack_bf16x2(vb[2 * j] - h0, vb[2 * j + 1] - h1);
            rh[slotA[j]] = h;
            rl[slotA[j]] = l;
        }
        rh[9] = rh[11] = rh[13] = rh[15] = 0u;
        rl[9] = rl[11] = rl[13] = rl[15] = 0u;
    }
    __syncthreads();

    // phase 2: raw dead; build B fragments (verified R9 layout) in sAux
    for (int e = tid; e < 6912; e += 256) {
        int tap = e / 768;
        int rm = e % 768;
        int ks = rm / 384; rm %= 384;
        int hl = rm / 192; rm %= 192;
        int nt = rm / 64;
        int l2 = rm % 64;
        int ln = l2 >> 1, rr = l2 & 1;
        int gg = ln >> 2, tt = ln & 3;
        int oc = nt * 8 + gg;
        int ic0 = ks * 16 + 2 * tt + rr * 8;
        float v0 = 0.f, v1 = 0.f;
        if (ic0 < 24) {
            float wv = w[(oc * 24 + ic0) * 9 + tap];
            float h = bf16f(wv);
            v0 = (hl == 0) ? h : (wv - h);
        }
        if (ic0 + 1 < 24) {
            float wv = w[(oc * 24 + ic0 + 1) * 9 + tap];
            float h = bf16f(wv);
            v1 = (hl == 0) ? h : (wv - h);
        }
        sAux[e] = pack_bf16x2(v0, v1);
    }
    __syncthreads();

    // phase 3: per-warp patch loop
    const uint2* sHi2 = (const uint2*)sHi;
    const uint2* sLo2 = (const uint2*)sLo;
    float* ob = out + (size_t)b * 24 * S * S;
    for (int p = wid; p < npx; p += 8) {
        int colb = p * 4 + (g & 3);
        int pr = g >> 2;
        float c0[4] = {0.f, 0.f, 0.f, 0.f};
        float c1[4] = {0.f, 0.f, 0.f, 0.f};
        float c2[4] = {0.f, 0.f, 0.f, 0.f};
        #pragma unroll
        for (int ky = 0; ky < 3; ky++) {
            #pragma unroll
            for (int kx = 0; kx < 3; kx++) {
                int tap = ky * 3 + kx;
                int pixA = (pr + ky) * Wp + colb + kx;
                int pixB = pixA + 2 * Wp;
                #pragma unroll
                for (int ks = 0; ks < 2; ks++) {
                    uint2 hA = sHi2[pixA * 9 + ks * 4 + tg];
                    uint2 hB = sHi2[pixB * 9 + ks * 4 + tg];
                    uint2 lA = sLo2[pixA * 9 + ks * 4 + tg];
                    uint2 lB = sLo2[pixB * 9 + ks * 4 + tg];
                    uint32_t ah[4] = {hA.x, hB.x, hA.y, hB.y};
                    uint32_t al[4] = {lA.x, lB.x, lA.y, lB.y};
                    const uint2* bh = (const uint2*)(sAux + (tap * 4 + ks * 2) * 192);
                    const uint2* bl = (const uint2*)(sAux + (tap * 4 + ks * 2 + 1) * 192);
                    uint2 bh0 = bh[lane], bh1 = bh[32 + lane], bh2 = bh[64 + lane];
                    uint2 bl0 = bl[lane], bl1 = bl[32 + lane], bl2 = bl[64 + lane];
                    mma_bf16(c0, ah, bh0.x, bh0.y);
                    mma_bf16(c1, ah, bh1.x, bh1.y);
                    mma_bf16(c2, ah, bh2.x, bh2.y);
                    mma_bf16(c0, al, bh0.x, bh0.y);
                    mma_bf16(c1, al, bh1.x, bh1.y);
                    mma_bf16(c2, al, bh2.x, bh2.y);
                    mma_bf16(c0, ah, bl0.x, bl0.y);
                    mma_bf16(c1, ah, bl1.x, bl1.y);
                    mma_bf16(c2, ah, bl2.x, bl2.y);
                }
            }
        }
        // epilogue: residual reconstructed hi+lo, + bias, relu, masked stores
        int gx = colb;
        int gy0 = y0 + pr, gy1 = gy0 + 2;
        bool v0ok = (gy0 < S) && (gx < S);
        bool v1ok = (gy1 < S) && (gx < S);
        const uint32_t* ch0 = sHi + ((pr + 1) * Wp + colb + 1) * 18;
        const uint32_t* cl0 = sLo + ((pr + 1) * Wp + colb + 1) * 18;
        const uint32_t* ch1 = ch0 + 2 * Wp * 18;
        const uint32_t* cl1 = cl0 + 2 * Wp * 18;
        #pragma unroll
        for (int nt = 0; nt < 3; nt++) {
            const float* cp = (nt == 0) ? c0 : (nt == 1) ? c1 : c2;
            int oc = nt * 8 + 2 * tg;
            int j = nt * 4 + tg;
            int slot = (j < 8) ? (2 * (j & 3) + (j >> 2)) : (8 + 2 * (j - 8));
            float b0v = sBias[oc], b1v = sBias[oc + 1];
            if (v0ok) {
                float h0, h1, l0, l1;
                unpack_bf16x2(ch0[slot], h0, h1);
                unpack_bf16x2(cl0[slot], l0, l1);
                ob[((size_t)oc * S + gy0) * S + gx] =
                    fmaxf(cp[0] + h0 + l0 + b0v, 0.f);
                ob[((size_t)(oc + 1) * S + gy0) * S + gx] =
                    fmaxf(cp[1] + h1 + l1 + b1v, 0.f);
            }
            if (v1ok) {
                float h0, h1, l0, l1;
                unpack_bf16x2(ch1[slot], h0, h1);
                unpack_bf16x2(cl1[slot], l0, l1);
                ob[((size_t)oc * S + gy1) * S + gx] =
                    fmaxf(cp[2] + h0 + l0 + b0v, 0.f);
                ob[((size_t)(oc + 1) * S + gy1) * S + gx] =
                    fmaxf(cp[3] + h1 + l1 + b1v, 0.f);
            }
        }
    }
}

// ---------------- fused epilogue: 1x1 conv + sigmoid + flow + ct + grid + warp --------
__global__ __launch_bounds__(256) void k_final(const float* __restrict__ inp,
                                               const float* __restrict__ c3w,
                                               const float* __restrict__ c3b,
                                               float* __restrict__ outp) {
    __shared__ float s_w[KOBJ * 24];
    __shared__ float s_b[KOBJ];
    __shared__ float s_ot[KOBJ * 2];
    __shared__ float s_ct[2];
    int b = blockIdx.y, tid = threadIdx.x;
    int p = blockIdx.x * 256 + tid;
    for (int i = tid; i < KOBJ * 24; i += 256) s_w[i] = c3w[i];
    if (tid < KOBJ) s_b[tid] = c3b[tid];
    if (tid < KOBJ * 2) s_ot[tid] = g_ot[b * 40 + tid];
    if (tid < 2) s_ct[tid] = g_ct[b * 2 + tid];
    __syncthreads();
    if (p >= 7056) return;
    const float* mp = g_m84b + (size_t)b * 24 * 7056 + p;
    float mv[24];
    #pragma unroll
    for (int c = 0; c < 24; c++) mv[c] = mp[c * 7056];
    float fy = s_ct[0], fx = s_ct[1];
    #pragma unroll 4
    for (int k = 0; k < KOBJ; k++) {
        float s = s_b[k];
        #pragma unroll
        for (int c = 0; c < 24; c++) s += mv[c] * s_w[k * 24 + c];
        float mask = 1.f / (1.f + __expf(-s));
        fy += mask * s_ot[k * 2];
        fx += mask * s_ot[k * 2 + 1];
    }
    int gy = p / 84, gx = p % 84;
    const float isf = 0.01f * 84.0f;
    float ys = isf * fy + (float)gy;
    float xs = isf * fx + (float)gx;
    const float* src = inp + (size_t)b * 14112 + 7056;
    int x0 = min(max((int)floorf(xs), 0), 83);
    int y0 = min(max((int)floorf(ys), 0), 83);
    int x1 = min(x0 + 1, 83);
    int y1 = min(y0 + 1, 83);
    float Ia = src[y0 * 84 + x0], Ib = src[y1 * 84 + x0];
    float Ic = src[y0 * 84 + x1], Id = src[y1 * 84 + x1];
    float xc = fminf(fmaxf(xs, 0.f), 83.f);
    float yc = fminf(fmaxf(ys, 0.f), 83.f);
    float x0f = (float)x0, x1f = (float)x1, y0f = (float)y0, y1f = (float)y1;
    float o = (x1f - xc) * (y1f - yc) * Ia + (x1f - xc) * (yc - y0f) * Ib +
              (xc - x0f) * (y1f - yc) * Ic + (xc - x0f) * (yc - y0f) * Id;
    outp[(size_t)b * 7056 + p] = o;
}

// ---------------- launch ----------------
extern "C" void kernel_launch(void* const* d_in, const int* in_sizes, int n_in,
                              void* d_out, int out_size) {
    const float* inp = (const float*)d_in[0];
    const float* cw1 = (const float*)d_in[1];
    const float* cb1 = (const float*)d_in[2];
    const float* cw2 = (const float*)d_in[3];
    const float* cb2 = (const float*)d_in[4];
    const float* cw3 = (const float*)d_in[5];
    const float* cb3 = (const float*)d_in[6];
    const float* fcw = (const float*)d_in[7];
    const float* fcb = (const float*)d_in[8];
    const float* otw = (const float*)d_in[9];
    const float* otb = (const float*)d_in[10];
    const float* ctw = (const float*)d_in[11];
    const float* ctb = (const float*)d_in[12];
    const float* m1w = (const float*)d_in[13];
    const float* m1b = (const float*)d_in[14];
    const float* c1w = (const float*)d_in[15];
    const float* c1b = (const float*)d_in[16];
    const float* c2w = (const float*)d_in[17];
    const float* c2b = (const float*)d_in[18];
    const float* c3w = (const float*)d_in[19];
    const float* c3b = (const float*)d_in[20];
    float* outp = (float*)d_out;

    cudaFuncSetAttribute(k_conv1,  cudaFuncAttributeMaxDynamicSharedMemorySize, 72832);
    cudaFuncSetAttribute(k_conv23, cudaFuncAttributeMaxDynamicSharedMemorySize, 168192);
    cudaFuncSetAttribute(k_upconv_hmma2, cudaFuncAttributeMaxDynamicSharedMemorySize, 102048);

    float *p_h3, *p_x, *p_fcpart, *p_m21, *p_m42b, *p_m84b;
    cudaGetSymbolAddress((void**)&p_h3,     g_h3);
    cudaGetSymbolAddress((void**)&p_x,      g_x);
    cudaGetSymbolAddress((void**)&p_fcpart, g_fcpart);
    cudaGetSymbolAddress((void**)&p_m21,    g_m21);
    cudaGetSymbolAddress((void**)&p_m42b,   g_m42b);
    cudaGetSymbolAddress((void**)&p_m84b,   g_m84b);

    // encoder
    k_conv1<<<Bsz, 256, 72832>>>(inp, cw1, cb1);
    k_conv23<<<Bsz, 256, 168192>>>(cw2, cb2, cw3, cb3);
    // fc: split-K=7 + fused reduce(relu)+heads
    k_gemm2<<<dim3(EMB / GBN, Bsz / GBM, 7), 256>>>(p_h3, fcw, fcb, p_fcpart,
                                                    Bsz, EMB, 3136, 448, 0);
    k_fcredheads<<<Bsz, 256>>>(fcb, otw, otb, ctw, ctb);
    // mask fc
    k_gemm2<<<dim3((10584 + GBN - 1) / GBN, Bsz / GBM, 1), 256>>>(p_x, m1w, m1b, p_m21,
                                                                  Bsz, 10584, EMB, EMB, 0);
    // decoder: bf16 hi/lo tiles in smem
    // conv42: Wp=46, tileU=6*46*18=4968, smem=(2*4968+6912+24)*4=67488, bands=11, npx=11
    k_upconv_hmma2<<<dim3(11, Bsz), 256, 67488>>>(p_m21, c1w, c1b, p_m42b,
                                                  21, 42, 46, 11, 20.f / 41.f, 4968);
    // conv84: Wp=86, tileU=6*86*18=9288, smem=(2*9288+6912+24)*4=102048, bands=21, npx=21
    k_upconv_hmma2<<<dim3(21, Bsz), 256, 102048>>>(p_m42b, c2w, c2b, p_m84b,
                                                   42, 84, 86, 21, 41.f / 83.f, 9288);
    // fused: 1x1 conv + sigmoid masks + flow + warp
    k_final<<<dim3(28, Bsz), 256>>>(inp, c3w, c3b, outp);
    (void)in_sizes; (void)n_in; (void)out_size;
}

// round 13
// speedup vs baseline: 1.7329x; 1.1100x over previous
#include <cuda_runtime.h>
#include <cuda_bf16.h>
#include <math.h>
#include <stdint.h>

#define Bsz 512
#define HH 84
#define WW 84
#define KOBJ 20
#define DEPTH 24
#define EMB 512

// ---------------- scratch (static device globals; no allocations) ----------------
__device__ float g_h1[Bsz * 32 * 20 * 20];
__device__ float g_h3[Bsz * 64 * 7 * 7];
__device__ float g_fcpart[7 * Bsz * EMB];
__device__ float g_x [Bsz * EMB];
__device__ float g_ot[Bsz * KOBJ * 2];
__device__ float g_ct[Bsz * 2];
__device__ float g_m21 [Bsz * DEPTH * 21 * 21];
__device__ float g_m42b[Bsz * DEPTH * 42 * 42];
__device__ float g_m84b[Bsz * DEPTH * 84 * 84];

// ---------------- helpers ----------------
__device__ __forceinline__ uint32_t pack_bf16x2(float lo, float hi) {
    uint32_t r;
    asm("cvt.rn.bf16x2.f32 %0, %1, %2;" : "=r"(r) : "f"(hi), "f"(lo));
    return r;  // low16 = bf16(lo), high16 = bf16(hi)
}
__device__ __forceinline__ void unpack_bf16x2(uint32_t u, float& lo, float& hi) {
    lo = __uint_as_float(u << 16);
    hi = __uint_as_float(u & 0xFFFF0000u);
}
__device__ __forceinline__ float bf16f(float v) {
    return __bfloat162float(__float2bfloat16(v));
}
__device__ __forceinline__ void mma_bf16(float c[4], const uint32_t a[4],
                                         uint32_t b0, uint32_t b1) {
    asm volatile("mma.sync.aligned.m16n8k16.row.col.f32.bf16.bf16.f32 "
        "{%0,%1,%2,%3}, {%4,%5,%6,%7}, {%8,%9}, {%0,%1,%2,%3};"
        : "+f"(c[0]), "+f"(c[1]), "+f"(c[2]), "+f"(c[3])
        : "r"(a[0]), "r"(a[1]), "r"(a[2]), "r"(a[3]), "r"(b0), "r"(b1));
}
__device__ __forceinline__ void mma_bf16_k8(float c[4], uint32_t a0, uint32_t a1,
                                            uint32_t b0) {
    asm volatile("mma.sync.aligned.m16n8k8.row.col.f32.bf16.bf16.f32 "
        "{%0,%1,%2,%3}, {%4,%5}, {%6}, {%0,%1,%2,%3};"
        : "+f"(c[0]), "+f"(c[1]), "+f"(c[2]), "+f"(c[3])
        : "r"(a0), "r"(a1), "r"(b0));
}

// ---------------- conv1: [B,2,84,84] k8 s4 -> [B,32,20,20], relu ----------------
__global__ __launch_bounds__(256) void k_conv1(const float* __restrict__ inp,
                                               const float* __restrict__ w,
                                               const float* __restrict__ bias) {
    extern __shared__ float sm[];
    float* sIn = sm;          // 14112
    float* sW  = sm + 14112;  // 4096
    int b = blockIdx.x, tid = threadIdx.x;
    const float* ip = inp + b * 14112;
    for (int i = tid; i < 14112; i += 256) sIn[i] = ip[i];
    for (int i = tid; i < 4096;  i += 256) sW[i]  = w[i];
    __syncthreads();
    for (int o = tid; o < 3200; o += 256) {
        int oc = o / 100; int r = o % 100;
        int oy = (r / 10) * 2, ox = (r % 10) * 2;
        float a00 = 0.f, a01 = 0.f, a10 = 0.f, a11 = 0.f;
        for (int ic = 0; ic < 2; ic++) {
            const float* wp  = sW + (oc * 2 + ic) * 64;
            const float* inb = sIn + ic * 7056;
            #pragma unroll
            for (int ky = 0; ky < 8; ky++) {
                const float* r0 = inb + (oy * 4 + ky) * 84 + ox * 4;
                const float* r1 = r0 + 4 * 84;
                float v0[12], v1[12];
                #pragma unroll
                for (int j = 0; j < 12; j++) { v0[j] = r0[j]; v1[j] = r1[j]; }
                #pragma unroll
                for (int kx = 0; kx < 8; kx++) {
                    float ww = wp[ky * 8 + kx];
                    a00 += v0[kx] * ww;  a01 += v0[kx + 4] * ww;
                    a10 += v1[kx] * ww;  a11 += v1[kx + 4] * ww;
                }
            }
        }
        float bb = bias[oc];
        float* op = g_h1 + b * 12800 + oc * 400 + oy * 20 + ox;
        op[0]  = fmaxf(a00 + bb, 0.f); op[1]  = fmaxf(a01 + bb, 0.f);
        op[20] = fmaxf(a10 + bb, 0.f); op[21] = fmaxf(a11 + bb, 0.f);
    }
}

// ---------------- conv2+conv3 fused (h2 stays in smem) ----------------
__global__ __launch_bounds__(256) void k_conv23(const float* __restrict__ w2,
                                                const float* __restrict__ b2,
                                                const float* __restrict__ w3,
                                                const float* __restrict__ b3) {
    extern __shared__ float sm[];
    float* sIn1 = sm;
    float* sW2  = sm + 12800;
    float* sH2  = sm + 36864;
    int b = blockIdx.x, tid = threadIdx.x;
    const float* ip = g_h1 + b * 12800;
    for (int i = tid; i < 12800; i += 256) sIn1[i] = ip[i];
    for (int ch = 0; ch < 2; ch++) {
        __syncthreads();
        for (int i = tid; i < 16384; i += 256) sW2[i] = w2[ch * 16384 + i];
        __syncthreads();
        if (tid < 216) {
            int ocg = tid / 27; int r = tid % 27; int oy = r / 3; int oxg = (r % 3) * 3;
            float acc[4][3] = {};
            int iy0 = oy * 2, ix0 = oxg * 2;
            for (int ic = 0; ic < 32; ic++) {
                #pragma unroll
                for (int ky = 0; ky < 4; ky++) {
                    const float* rp = sIn1 + ic * 400 + (iy0 + ky) * 20 + ix0;
                    float v[8];
                    #pragma unroll
                    for (int j = 0; j < 8; j++) v[j] = rp[j];
                    #pragma unroll
                    for (int u = 0; u < 4; u++) {
                        const float* wp = sW2 + ((ocg * 4 + u) * 32 + ic) * 16 + ky * 4;
                        #pragma unroll
                        for (int kx = 0; kx < 4; kx++) {
                            float ww = wp[kx];
                            acc[u][0] += v[kx] * ww;
                            acc[u][1] += v[kx + 2] * ww;
                            acc[u][2] += v[kx + 4] * ww;
                        }
                    }
                }
            }
            #pragma unroll
            for (int u = 0; u < 4; u++) {
                int oc = ch * 32 + ocg * 4 + u;
                float bb = b2[oc];
                float* op = sH2 + oc * 81 + oy * 9 + oxg;
                #pragma unroll
                for (int j = 0; j < 3; j++) op[j] = fmaxf(acc[u][j] + bb, 0.f);
            }
        }
    }
    __syncthreads();
    for (int i = tid; i < 36864; i += 256) sm[i] = w3[i];
    __syncthreads();
    for (int it = tid; it < 448; it += 256) {
        int oc = it / 7, oy = it % 7;
        float acc[7] = {};
        for (int ic = 0; ic < 64; ic++) {
            const float* wp = sm + (oc * 64 + ic) * 9;
            #pragma unroll
            for (int ky = 0; ky < 3; ky++) {
                const float* rp = sH2 + ic * 81 + (oy + ky) * 9;
                float v[9];
                #pragma unroll
                for (int j = 0; j < 9; j++) v[j] = rp[j];
                #pragma unroll
                for (int kx = 0; kx < 3; kx++) {
                    float ww = wp[ky * 3 + kx];
                    #pragma unroll
                    for (int j = 0; j < 7; j++) acc[j] += v[j + kx] * ww;
                }
            }
        }
        float bb = b3[oc];
        float* op = g_h3 + b * 3136 + oc * 49 + oy * 7;
        #pragma unroll
        for (int j = 0; j < 7; j++) op[j] = fmaxf(acc[j] + bb, 0.f);
    }
}

// ---------------- GEMM v2 ----------------
#define GBM 128
#define GBN 64
#define GBK 16
__global__ __launch_bounds__(256) void k_gemm2(const float* __restrict__ A,
                                               const float* __restrict__ W,
                                               const float* __restrict__ bias,
                                               float* __restrict__ C,
                                               int M, int N, int K, int Kc, int relu) {
    __shared__ float As[GBK][GBM];
    __shared__ float Ws[GBK][GBN];
    int bm = blockIdx.y * GBM, bn = blockIdx.x * GBN;
    int ks = blockIdx.z * Kc;
    int ke = min(ks + Kc, K);
    int tid = threadIdx.x;
    float acc[8][4];
    #pragma unroll
    for (int i = 0; i < 8; i++)
        #pragma unroll
        for (int j = 0; j < 4; j++) acc[i][j] = 0.f;

    int tm = (tid / 16) * 8, tn = (tid % 16) * 4;

    for (int k0 = ks; k0 < ke; k0 += GBK) {
        #pragma unroll
        for (int l = tid; l < 512; l += 256) {
            int m = l >> 2, kq = (l & 3) << 2;
            float4 v = *(const float4*)(A + (size_t)(bm + m) * K + k0 + kq);
            As[kq + 0][m] = v.x; As[kq + 1][m] = v.y;
            As[kq + 2][m] = v.z; As[kq + 3][m] = v.w;
        }
        {
            int n = tid >> 2, kq = (tid & 3) << 2;
            int gn = bn + n;
            float4 v = make_float4(0.f, 0.f, 0.f, 0.f);
            if (gn < N) v = *(const float4*)(W + (size_t)gn * K + k0 + kq);
            Ws[kq + 0][n] = v.x; Ws[kq + 1][n] = v.y;
            Ws[kq + 2][n] = v.z; Ws[kq + 3][n] = v.w;
        }
        __syncthreads();
        #pragma unroll
        for (int k = 0; k < GBK; k++) {
            float4 a0 = *(const float4*)&As[k][tm];
            float4 a1 = *(const float4*)&As[k][tm + 4];
            float4 bv = *(const float4*)&Ws[k][tn];
            float a[8] = {a0.x, a0.y, a0.z, a0.w, a1.x, a1.y, a1.z, a1.w};
            float bb[4] = {bv.x, bv.y, bv.z, bv.w};
            #pragma unroll
            for (int i = 0; i < 8; i++)
                #pragma unroll
                for (int j = 0; j < 4; j++) acc[i][j] += a[i] * bb[j];
        }
        __syncthreads();
    }

    if (Kc >= K) {
        #pragma unroll
        for (int i = 0; i < 8; i++) {
            int gm = bm + tm + i;
            #pragma unroll
            for (int j = 0; j < 4; j++) {
                int gn = bn + tn + j;
                if (gn < N) {
                    float v = acc[i][j] + bias[gn];
                    if (relu) v = fmaxf(v, 0.f);
                    C[(size_t)gm * N + gn] = v;
                }
            }
        }
    } else {
        float* Cp = C + (size_t)blockIdx.z * M * N;
        #pragma unroll
        for (int i = 0; i < 8; i++) {
            int gm = bm + tm + i;
            #pragma unroll
            for (int j = 0; j < 4; j++) {
                int gn = bn + tn + j;
                if (gn < N) Cp[(size_t)gm * N + gn] = acc[i][j];
            }
        }
    }
}

// ---------------- fc reduce + heads (warp-parallel heads) ----------------
__global__ __launch_bounds__(256) void k_fcredheads(const float* __restrict__ fcb,
                                                    const float* __restrict__ otw,
                                                    const float* __restrict__ otb,
                                                    const float* __restrict__ ctw,
                                                    const float* __restrict__ ctb) {
    __shared__ float sx[EMB];
    int b = blockIdx.x, tid = threadIdx.x;
    int lane = tid & 31, wid = tid >> 5;
    for (int i = tid; i < EMB; i += 256) {
        float s = fcb[i];
        #pragma unroll
        for (int p = 0; p < 7; p++) s += g_fcpart[p * Bsz * EMB + b * EMB + i];
        float v = fmaxf(s, 0.f);
        g_x[b * EMB + i] = v;
        sx[i] = v;
    }
    __syncthreads();
    #pragma unroll
    for (int j = 0; j < 6; j++) {
        int o = j * 8 + wid;
        if (o < 42) {
            const float* wp = (o < 40) ? (otw + o * EMB) : (ctw + (o - 40) * EMB);
            float s = 0.f;
            #pragma unroll
            for (int k = lane; k < EMB; k += 32) s += sx[k] * wp[k];
            #pragma unroll
            for (int d = 16; d > 0; d >>= 1) s += __shfl_xor_sync(0xFFFFFFFFu, s, d);
            if (lane == 0) {
                if (o < 40) g_ot[b * 40 + o] = s + otb[o];
                else        g_ct[b * 2 + (o - 40)] = s + ctb[o - 40];
            }
        }
    }
}

// ==== fused upsample + residual 3x3 conv, bf16 3-term, k16+k8 dense, B hoisted ====
// Pixel record = 12 u32: ks0 pairs at uint2 idx tg (slots {0,2,4,6,1,3,5,7} for
// j=0..7), ks1 singles at u32 slots 8..11 (j=8..11). B frags per tap: 576 u32
// (ks0: 384 as [hl][nt][lane] uint2; ks1: 192 as [hl][nt][lane] u32).
__global__ __launch_bounds__(256, 2) void k_upconv_hmma3(
        const float* __restrict__ src, const float* __restrict__ w,
        const float* __restrict__ bias, float* __restrict__ out,
        int inS, int S, int Wp, int npx, float scale, int tileU, int auxU) {
    extern __shared__ uint32_t smu[];
    uint32_t* sHi = smu;
    uint32_t* sLo = smu + tileU;
    uint32_t* sAux = smu + 2 * tileU;        // raw staging then B fragments (5184)
    float* sRawF = (float*)sAux;
    float* sBias = (float*)(sAux + auxU);
    int tid = threadIdx.x, lane = tid & 31, wid = tid >> 5;
    int b = blockIdx.y, band = blockIdx.x;
    int y0 = band * 4;
    int g = lane >> 2, tg = lane & 3;

    // phase 0: stage raw src rows [ic][6][inS] + bias
    int sy0 = (int)(fmaxf((float)(y0 - 1), 0.f) * scale);
    const float* srcb = src + (size_t)b * 24 * inS * inS;
    int rawTot = 24 * 6 * inS;
    for (int e = tid; e < rawTot; e += 256) {
        int ic = e / (6 * inS);
        int r2 = e % (6 * inS);
        int ry = r2 / inS, x = r2 % inS;
        int sy = sy0 + ry;
        sRawF[e] = (sy < inS) ? srcb[(size_t)ic * inS * inS + sy * inS + x] : 0.f;
    }
    if (tid < 24) sBias[tid] = bias[tid];
    __syncthreads();

    // phase 1: bilinear upsample -> bf16 hi/lo 12-u32 records
    for (int pix = tid; pix < 6 * Wp; pix += 256) {
        int r = pix / Wp, c = pix - r * Wp;
        int gy = y0 + r - 1, gx = c - 1;
        uint32_t* rh = sHi + pix * 12;
        uint32_t* rl = sLo + pix * 12;
        float vb[24];
        if (gy >= 0 && gy < S && gx >= 0 && gx < S) {
            float py = gy * scale;
            int yl = min((int)py, inS - 2);
            float wy = py - (float)yl;
            float px = gx * scale;
            int xl = min((int)px, inS - 2);
            float wx = px - (float)xl;
            const float* base = sRawF + (yl - sy0) * inS + xl;
            #pragma unroll
            for (int ic = 0; ic < 24; ic++) {
                const float* rp = base + ic * (6 * inS);
                float v00 = rp[0], v01 = rp[1], v10 = rp[inS], v11 = rp[inS + 1];
                vb[ic] = (1.f - wy) * ((1.f - wx) * v00 + wx * v01) +
                         wy * ((1.f - wx) * v10 + wx * v11);
            }
        } else {
            #pragma unroll
            for (int ic = 0; ic < 24; ic++) vb[ic] = 0.f;
        }
        const int slotA[12] = {0, 2, 4, 6, 1, 3, 5, 7, 8, 9, 10, 11};
        #pragma unroll
        for (int j = 0; j < 12; j++) {
            uint32_t h = pack_bf16x2(vb[2 * j], vb[2 * j + 1]);
            float h0, h1;
            unpack_bf16x2(h, h0, h1);
            uint32_t l = pack_bf16x2(vb[2 * j] - h0, vb[2 * j + 1] - h1);
            rh[slotA[j]] = h;
            rl[slotA[j]] = l;
        }
    }
    __syncthreads();

    // phase 2: raw dead; build B fragments in sAux (5184 u32)
    for (int e = tid; e < 5184; e += 256) {
        int tap = e / 576;
        int r = e % 576;
        int nt, hl, ic0, oc;
        if (r < 384) {
            int rr = r & 1; int q = r >> 1;
            int ln = q & 31; int hn = q >> 5;
            nt = hn % 3; hl = hn / 3;
            oc = nt * 8 + (ln >> 2);
            ic0 = 2 * (ln & 3) + 8 * rr;
        } else {
            int u = r - 384;
            int ln = u & 31; int hn = u >> 5;
            nt = hn % 3; hl = hn / 3;
            oc = nt * 8 + (ln >> 2);
            ic0 = 16 + 2 * (ln & 3);
        }
        float wv0 = w[(oc * 24 + ic0) * 9 + tap];
        float wv1 = w[(oc * 24 + ic0 + 1) * 9 + tap];
        float h0 = bf16f(wv0), h1 = bf16f(wv1);
        float v0 = hl ? (wv0 - h0) : h0;
        float v1 = hl ? (wv1 - h1) : h1;
        smu[2 * tileU + e] = pack_bf16x2(v0, v1);
    }
    __syncthreads();

    // phase 3: k-substep-outer, patch-inner loop (up to 3 patches per warp)
    const uint2* sHi2 = (const uint2*)sHi;
    const uint2* sLo2 = (const uint2*)sLo;
    int pr = g >> 2;
    int pix0[3]; bool pv[3]; int colb_[3];
    #pragma unroll
    for (int pi = 0; pi < 3; pi++) {
        int p = wid + 8 * pi;
        pv[pi] = (p < npx);
        int pp = pv[pi] ? p : 0;
        colb_[pi] = pp * 4 + (g & 3);
        pix0[pi] = pr * Wp + colb_[pi];
    }
    float acc[3][12];
    #pragma unroll
    for (int pi = 0; pi < 3; pi++)
        #pragma unroll
        for (int q = 0; q < 12; q++) acc[pi][q] = 0.f;

    #pragma unroll
    for (int ky = 0; ky < 3; ky++) {
        #pragma unroll
        for (int kx = 0; kx < 3; kx++) {
            int tap = ky * 3 + kx;
            const uint2* b16 = (const uint2*)(sAux + tap * 576);
            uint2 bh0 = b16[lane],       bh1 = b16[lane + 32],  bh2 = b16[lane + 64];
            uint2 bl0 = b16[lane + 96],  bl1 = b16[lane + 128], bl2 = b16[lane + 160];
            #pragma unroll
            for (int pi = 0; pi < 3; pi++) {
                if (!pv[pi]) continue;
                int pixA = pix0[pi] + ky * Wp + kx;
                int pixB = pixA + 2 * Wp;
                uint2 hA = sHi2[pixA * 6 + tg], hB = sHi2[pixB * 6 + tg];
                uint2 lA = sLo2[pixA * 6 + tg], lB = sLo2[pixB * 6 + tg];
                uint32_t ah[4] = {hA.x, hB.x, hA.y, hB.y};
                uint32_t al[4] = {lA.x, lB.x, lA.y, lB.y};
                mma_bf16(acc[pi] + 0, ah, bh0.x, bh0.y);
                mma_bf16(acc[pi] + 4, ah, bh1.x, bh1.y);
                mma_bf16(acc[pi] + 8, ah, bh2.x, bh2.y);
                mma_bf16(acc[pi] + 0, al, bh0.x, bh0.y);
                mma_bf16(acc[pi] + 4, al, bh1.x, bh1.y);
                mma_bf16(acc[pi] + 8, al, bh2.x, bh2.y);
                mma_bf16(acc[pi] + 0, ah, bl0.x, bl0.y);
                mma_bf16(acc[pi] + 4, ah, bl1.x, bl1.y);
                mma_bf16(acc[pi] + 8, ah, bl2.x, bl2.y);
            }
            const uint32_t* b8 = sAux + tap * 576 + 384;
            uint32_t c8h0 = b8[lane],      c8h1 = b8[lane + 32],  c8h2 = b8[lane + 64];
            uint32_t c8l0 = b8[lane + 96], c8l1 = b8[lane + 128], c8l2 = b8[lane + 160];
            #pragma unroll
            for (int pi = 0; pi < 3; pi++) {
                if (!pv[pi]) continue;
                int pixA = pix0[pi] + ky * Wp + kx;
                int pixB = pixA + 2 * Wp;
                uint32_t a0h = sHi[pixA * 12 + 8 + tg], a1h = sHi[pixB * 12 + 8 + tg];
                uint32_t a0l = sLo[pixA * 12 + 8 + tg], a1l = sLo[pixB * 12 + 8 + tg];
                mma_bf16_k8(acc[pi] + 0, a0h, a1h, c8h0);
                mma_bf16_k8(acc[pi] + 4, a0h, a1h, c8h1);
                mma_bf16_k8(acc[pi] + 8, a0h, a1h, c8h2);
                mma_bf16_k8(acc[pi] + 0, a0l, a1l, c8h0);
                mma_bf16_k8(acc[pi] + 4, a0l, a1l, c8h1);
                mma_bf16_k8(acc[pi] + 8, a0l, a1l, c8h2);
                mma_bf16_k8(acc[pi] + 0, a0h, a1h, c8l0);
                mma_bf16_k8(acc[pi] + 4, a0h, a1h, c8l1);
                mma_bf16_k8(acc[pi] + 8, a0h, a1h, c8l2);
            }
        }
    }

    // epilogue: residual reconstructed hi+lo, + bias, relu, masked stores
    float* ob = out + (size_t)b * 24 * S * S;
    #pragma unroll
    for (int pi = 0; pi < 3; pi++) {
        if (!pv[pi]) continue;
        int colb = colb_[pi];
        int gx = colb;
        int gy0 = y0 + pr, gy1 = gy0 + 2;
        bool v0ok = (gy0 < S) && (gx < S);
        bool v1ok = (gy1 < S) && (gx < S);
        const uint32_t* ch0 = sHi + ((pr + 1) * Wp + colb + 1) * 12;
        const uint32_t* cl0 = sLo + ((pr + 1) * Wp + colb + 1) * 12;
        const uint32_t* ch1 = ch0 + 2 * Wp * 12;
        const uint32_t* cl1 = cl0 + 2 * Wp * 12;
        #pragma unroll
        for (int nt = 0; nt < 3; nt++) {
            const float* cp = acc[pi] + nt * 4;
            int oc = nt * 8 + 2 * tg;
            int j = nt * 4 + tg;
            int slot = (j < 8) ? (2 * (j & 3) + (j >> 2)) : j;
            float b0v = sBias[oc], b1v = sBias[oc + 1];
            if (v0ok) {
                float h0, h1, l0, l1;
                unpack_bf16x2(ch0[slot], h0, h1);
                unpack_bf16x2(cl0[slot], l0, l1);
                ob[((size_t)oc * S + gy0) * S + gx] =
                    fmaxf(cp[0] + h0 + l0 + b0v, 0.f);
                ob[((size_t)(oc + 1) * S + gy0) * S + gx] =
                    fmaxf(cp[1] + h1 + l1 + b1v, 0.f);
            }
            if (v1ok) {
                float h0, h1, l0, l1;
                unpack_bf16x2(ch1[slot], h0, h1);
                unpack_bf16x2(cl1[slot], l0, l1);
                ob[((size_t)oc * S + gy1) * S + gx] =
                    fmaxf(cp[2] + h0 + l0 + b0v, 0.f);
                ob[((size_t)(oc + 1) * S + gy1) * S + gx] =
                    fmaxf(cp[3] + h1 + l1 + b1v, 0.f);
            }
        }
    }
}

// ---------------- fused epilogue: 1x1 conv + sigmoid + flow + ct + grid + warp --------
__global__ __launch_bounds__(256) void k_final(const float* __restrict__ inp,
                                               const float* __restrict__ c3w,
                                               const float* __restrict__ c3b,
                                               float* __restrict__ outp) {
    __shared__ float s_w[KOBJ * 24];
    __shared__ float s_b[KOBJ];
    __shared__ float s_ot[KOBJ * 2];
    __shared__ float s_ct[2];
    int b = blockIdx.y, tid = threadIdx.x;
    int p = blockIdx.x * 256 + tid;
    for (int i = tid; i < KOBJ * 24; i += 256) s_w[i] = c3w[i];
    if (tid < KOBJ) s_b[tid] = c3b[tid];
    if (tid < KOBJ * 2) s_ot[tid] = g_ot[b * 40 + tid];
    if (tid < 2) s_ct[tid] = g_ct[b * 2 + tid];
    __syncthreads();
    if (p >= 7056) return;
    const float* mp = g_m84b + (size_t)b * 24 * 7056 + p;
    float mv[24];
    #pragma unroll
    for (int c = 0; c < 24; c++) mv[c] = mp[c * 7056];
    float fy = s_ct[0], fx = s_ct[1];
    #pragma unroll 4
    for (int k = 0; k < KOBJ; k++) {
        float s = s_b[k];
        #pragma unroll
        for (int c = 0; c < 24; c++) s += mv[c] * s_w[k * 24 + c];
        float mask = 1.f / (1.f + __expf(-s));
        fy += mask * s_ot[k * 2];
        fx += mask * s_ot[k * 2 + 1];
    }
    int gy = p / 84, gx = p % 84;
    const float isf = 0.01f * 84.0f;
    float ys = isf * fy + (float)gy;
    float xs = isf * fx + (float)gx;
    const float* src = inp + (size_t)b * 14112 + 7056;
    int x0 = min(max((int)floorf(xs), 0), 83);
    int y0 = min(max((int)floorf(ys), 0), 83);
    int x1 = min(x0 + 1, 83);
    int y1 = min(y0 + 1, 83);
    float Ia = src[y0 * 84 + x0], Ib = src[y1 * 84 + x0];
    float Ic = src[y0 * 84 + x1], Id = src[y1 * 84 + x1];
    float xc = fminf(fmaxf(xs, 0.f), 83.f);
    float yc = fminf(fmaxf(ys, 0.f), 83.f);
    float x0f = (float)x0, x1f = (float)x1, y0f = (float)y0, y1f = (float)y1;
    float o = (x1f - xc) * (y1f - yc) * Ia + (x1f - xc) * (yc - y0f) * Ib +
              (xc - x0f) * (y1f - yc) * Ic + (xc - x0f) * (yc - y0f) * Id;
    outp[(size_t)b * 7056 + p] = o;
}

// ---------------- launch ----------------
extern "C" void kernel_launch(void* const* d_in, const int* in_sizes, int n_in,
                              void* d_out, int out_size) {
    const float* inp = (const float*)d_in[0];
    const float* cw1 = (const float*)d_in[1];
    const float* cb1 = (const float*)d_in[2];
    const float* cw2 = (const float*)d_in[3];
    const float* cb2 = (const float*)d_in[4];
    const float* cw3 = (const float*)d_in[5];
    const float* cb3 = (const float*)d_in[6];
    const float* fcw = (const float*)d_in[7];
    const float* fcb = (const float*)d_in[8];
    const float* otw = (const float*)d_in[9];
    const float* otb = (const float*)d_in[10];
    const float* ctw = (const float*)d_in[11];
    const float* ctb = (const float*)d_in[12];
    const float* m1w = (const float*)d_in[13];
    const float* m1b = (const float*)d_in[14];
    const float* c1w = (const float*)d_in[15];
    const float* c1b = (const float*)d_in[16];
    const float* c2w = (const float*)d_in[17];
    const float* c2b = (const float*)d_in[18];
    const float* c3w = (const float*)d_in[19];
    const float* c3b = (const float*)d_in[20];
    float* outp = (float*)d_out;

    cudaFuncSetAttribute(k_conv1,  cudaFuncAttributeMaxDynamicSharedMemorySize, 72832);
    cudaFuncSetAttribute(k_conv23, cudaFuncAttributeMaxDynamicSharedMemorySize, 168192);
    cudaFuncSetAttribute(k_upconv_hmma3, cudaFuncAttributeMaxDynamicSharedMemorySize, 73824);

    float *p_h3, *p_x, *p_fcpart, *p_m21, *p_m42b, *p_m84b;
    cudaGetSymbolAddress((void**)&p_h3,     g_h3);
    cudaGetSymbolAddress((void**)&p_x,      g_x);
    cudaGetSymbolAddress((void**)&p_fcpart, g_fcpart);
    cudaGetSymbolAddress((void**)&p_m21,    g_m21);
    cudaGetSymbolAddress((void**)&p_m42b,   g_m42b);
    cudaGetSymbolAddress((void**)&p_m84b,   g_m84b);

    // encoder
    k_conv1<<<Bsz, 256, 72832>>>(inp, cw1, cb1);
    k_conv23<<<Bsz, 256, 168192>>>(cw2, cb2, cw3, cb3);
    // fc: split-K=7 + fused reduce(relu)+heads
    k_gemm2<<<dim3(EMB / GBN, Bsz / GBM, 7), 256>>>(p_h3, fcw, fcb, p_fcpart,
                                                    Bsz, EMB, 3136, 448, 0);
    k_fcredheads<<<Bsz, 256>>>(fcb, otw, otb, ctw, ctb);
    // mask fc
    k_gemm2<<<dim3((10584 + GBN - 1) / GBN, Bsz / GBM, 1), 256>>>(p_x, m1w, m1b, p_m21,
                                                                  Bsz, 10584, EMB, EMB, 0);
    // decoder: dense k16+k8, B hoisted
    // conv42: Wp=46, tileU=6*46*12=3312, auxU=max(3024,5184)=5184
    //   smem=(2*3312+5184+24)*4=47328, bands=11, npx=11
    k_upconv_hmma3<<<dim3(11, Bsz), 256, 47328>>>(p_m21, c1w, c1b, p_m42b,
                                                  21, 42, 46, 11, 20.f / 41.f,
                                                  3312, 5184);
    // conv84: Wp=86, tileU=6*86*12=6192, auxU=max(6048,5184)=6048
    //   smem=(2*6192+6048+24)*4=73824, bands=21, npx=21
    k_upconv_hmma3<<<dim3(21, Bsz), 256, 73824>>>(p_m42b, c2w, c2b, p_m84b,
                                                  42, 84, 86, 21, 41.f / 83.f,
                                                  6192, 6048);
    // fused: 1x1 conv + sigmoid masks + flow + warp
    k_final<<<dim3(28, Bsz), 256>>>(inp, c3w, c3b, outp);
    (void)in_sizes; (void)n_in; (void)out_size;
}

// round 14
// speedup vs baseline: 1.7682x; 1.0203x over previous
#include <cuda_runtime.h>
#include <cuda_bf16.h>
#include <math.h>
#include <stdint.h>

#define Bsz 512
#define HH 84
#define WW 84
#define KOBJ 20
#define DEPTH 24
#define EMB 512

// ---------------- scratch (static device globals; no allocations) ----------------
__device__ float g_h1[Bsz * 32 * 20 * 20];
__device__ float g_h3[Bsz * 64 * 7 * 7];
__device__ float g_fcpart[7 * Bsz * EMB];
__device__ float g_x [Bsz * EMB];
__device__ float g_ot[Bsz * KOBJ * 2];
__device__ float g_ct[Bsz * 2];
__device__ float g_m21 [Bsz * DEPTH * 21 * 21];
__device__ float g_m42b[Bsz * DEPTH * 42 * 42];
__device__ float g_m84b[Bsz * DEPTH * 84 * 84];

// ---------------- helpers ----------------
__device__ __forceinline__ uint32_t pack_bf16x2(float lo, float hi) {
    uint32_t r;
    asm("cvt.rn.bf16x2.f32 %0, %1, %2;" : "=r"(r) : "f"(hi), "f"(lo));
    return r;  // low16 = bf16(lo), high16 = bf16(hi)
}
__device__ __forceinline__ void unpack_bf16x2(uint32_t u, float& lo, float& hi) {
    lo = __uint_as_float(u << 16);
    hi = __uint_as_float(u & 0xFFFF0000u);
}
__device__ __forceinline__ float bf16f(float v) {
    return __bfloat162float(__float2bfloat16(v));
}
__device__ __forceinline__ void mma_bf16(float c[4], const uint32_t a[4],
                                         uint32_t b0, uint32_t b1) {
    asm volatile("mma.sync.aligned.m16n8k16.row.col.f32.bf16.bf16.f32 "
        "{%0,%1,%2,%3}, {%4,%5,%6,%7}, {%8,%9}, {%0,%1,%2,%3};"
        : "+f"(c[0]), "+f"(c[1]), "+f"(c[2]), "+f"(c[3])
        : "r"(a[0]), "r"(a[1]), "r"(a[2]), "r"(a[3]), "r"(b0), "r"(b1));
}
__device__ __forceinline__ void mma_bf16_k8(float c[4], uint32_t a0, uint32_t a1,
                                            uint32_t b0) {
    asm volatile("mma.sync.aligned.m16n8k8.row.col.f32.bf16.bf16.f32 "
        "{%0,%1,%2,%3}, {%4,%5}, {%6}, {%0,%1,%2,%3};"
        : "+f"(c[0]), "+f"(c[1]), "+f"(c[2]), "+f"(c[3])
        : "r"(a0), "r"(a1), "r"(b0));
}

// ---------------- conv1: [B,2,84,84] k8 s4 -> [B,32,20,20], relu ----------------
__global__ __launch_bounds__(256) void k_conv1(const float* __restrict__ inp,
                                               const float* __restrict__ w,
                                               const float* __restrict__ bias) {
    extern __shared__ float sm[];
    float* sIn = sm;          // 14112
    float* sW  = sm + 14112;  // 4096
    int b = blockIdx.x, tid = threadIdx.x;
    const float* ip = inp + b * 14112;
    for (int i = tid; i < 14112; i += 256) sIn[i] = ip[i];
    for (int i = tid; i < 4096;  i += 256) sW[i]  = w[i];
    __syncthreads();
    for (int o = tid; o < 3200; o += 256) {
        int oc = o / 100; int r = o % 100;
        int oy = (r / 10) * 2, ox = (r % 10) * 2;
        float a00 = 0.f, a01 = 0.f, a10 = 0.f, a11 = 0.f;
        for (int ic = 0; ic < 2; ic++) {
            const float* wp  = sW + (oc * 2 + ic) * 64;
            const float* inb = sIn + ic * 7056;
            #pragma unroll
            for (int ky = 0; ky < 8; ky++) {
                const float* r0 = inb + (oy * 4 + ky) * 84 + ox * 4;
                const float* r1 = r0 + 4 * 84;
                float v0[12], v1[12];
                #pragma unroll
                for (int j = 0; j < 12; j++) { v0[j] = r0[j]; v1[j] = r1[j]; }
                #pragma unroll
                for (int kx = 0; kx < 8; kx++) {
                    float ww = wp[ky * 8 + kx];
                    a00 += v0[kx] * ww;  a01 += v0[kx + 4] * ww;
                    a10 += v1[kx] * ww;  a11 += v1[kx + 4] * ww;
                }
            }
        }
        float bb = bias[oc];
        float* op = g_h1 + b * 12800 + oc * 400 + oy * 20 + ox;
        op[0]  = fmaxf(a00 + bb, 0.f); op[1]  = fmaxf(a01 + bb, 0.f);
        op[20] = fmaxf(a10 + bb, 0.f); op[21] = fmaxf(a11 + bb, 0.f);
    }
}

// ---------------- conv2+conv3 fused (h2 stays in smem) ----------------
__global__ __launch_bounds__(256) void k_conv23(const float* __restrict__ w2,
                                                const float* __restrict__ b2,
                                                const float* __restrict__ w3,
                                                const float* __restrict__ b3) {
    extern __shared__ float sm[];
    float* sIn1 = sm;
    float* sW2  = sm + 12800;
    float* sH2  = sm + 36864;
    int b = blockIdx.x, tid = threadIdx.x;
    const float* ip = g_h1 + b * 12800;
    for (int i = tid; i < 12800; i += 256) sIn1[i] = ip[i];
    for (int ch = 0; ch < 2; ch++) {
        __syncthreads();
        for (int i = tid; i < 16384; i += 256) sW2[i] = w2[ch * 16384 + i];
        __syncthreads();
        if (tid < 216) {
            int ocg = tid / 27; int r = tid % 27; int oy = r / 3; int oxg = (r % 3) * 3;
            float acc[4][3] = {};
            int iy0 = oy * 2, ix0 = oxg * 2;
            for (int ic = 0; ic < 32; ic++) {
                #pragma unroll
                for (int ky = 0; ky < 4; ky++) {
                    const float* rp = sIn1 + ic * 400 + (iy0 + ky) * 20 + ix0;
                    float v[8];
                    #pragma unroll
                    for (int j = 0; j < 8; j++) v[j] = rp[j];
                    #pragma unroll
                    for (int u = 0; u < 4; u++) {
                        const float* wp = sW2 + ((ocg * 4 + u) * 32 + ic) * 16 + ky * 4;
                        #pragma unroll
                        for (int kx = 0; kx < 4; kx++) {
                            float ww = wp[kx];
                            acc[u][0] += v[kx] * ww;
                            acc[u][1] += v[kx + 2] * ww;
                            acc[u][2] += v[kx + 4] * ww;
                        }
                    }
                }
            }
            #pragma unroll
            for (int u = 0; u < 4; u++) {
                int oc = ch * 32 + ocg * 4 + u;
                float bb = b2[oc];
                float* op = sH2 + oc * 81 + oy * 9 + oxg;
                #pragma unroll
                for (int j = 0; j < 3; j++) op[j] = fmaxf(acc[u][j] + bb, 0.f);
            }
        }
    }
    __syncthreads();
    for (int i = tid; i < 36864; i += 256) sm[i] = w3[i];
    __syncthreads();
    for (int it = tid; it < 448; it += 256) {
        int oc = it / 7, oy = it % 7;
        float acc[7] = {};
        for (int ic = 0; ic < 64; ic++) {
            const float* wp = sm + (oc * 64 + ic) * 9;
            #pragma unroll
            for (int ky = 0; ky < 3; ky++) {
                const float* rp = sH2 + ic * 81 + (oy + ky) * 9;
                float v[9];
                #pragma unroll
                for (int j = 0; j < 9; j++) v[j] = rp[j];
                #pragma unroll
                for (int kx = 0; kx < 3; kx++) {
                    float ww = wp[ky * 3 + kx];
                    #pragma unroll
                    for (int j = 0; j < 7; j++) acc[j] += v[j + kx] * ww;
                }
            }
        }
        float bb = b3[oc];
        float* op = g_h3 + b * 3136 + oc * 49 + oy * 7;
        #pragma unroll
        for (int j = 0; j < 7; j++) op[j] = fmaxf(acc[j] + bb, 0.f);
    }
}

// ---------------- GEMM v2 ----------------
#define GBM 128
#define GBN 64
#define GBK 16
__global__ __launch_bounds__(256) void k_gemm2(const float* __restrict__ A,
                                               const float* __restrict__ W,
                                               const float* __restrict__ bias,
                                               float* __restrict__ C,
                                               int M, int N, int K, int Kc, int relu) {
    __shared__ float As[GBK][GBM];
    __shared__ float Ws[GBK][GBN];
    int bm = blockIdx.y * GBM, bn = blockIdx.x * GBN;
    int ks = blockIdx.z * Kc;
    int ke = min(ks + Kc, K);
    int tid = threadIdx.x;
    float acc[8][4];
    #pragma unroll
    for (int i = 0; i < 8; i++)
        #pragma unroll
        for (int j = 0; j < 4; j++) acc[i][j] = 0.f;

    int tm = (tid / 16) * 8, tn = (tid % 16) * 4;

    for (int k0 = ks; k0 < ke; k0 += GBK) {
        #pragma unroll
        for (int l = tid; l < 512; l += 256) {
            int m = l >> 2, kq = (l & 3) << 2;
            float4 v = *(const float4*)(A + (size_t)(bm + m) * K + k0 + kq);
            As[kq + 0][m] = v.x; As[kq + 1][m] = v.y;
            As[kq + 2][m] = v.z; As[kq + 3][m] = v.w;
        }
        {
            int n = tid >> 2, kq = (tid & 3) << 2;
            int gn = bn + n;
            float4 v = make_float4(0.f, 0.f, 0.f, 0.f);
            if (gn < N) v = *(const float4*)(W + (size_t)gn * K + k0 + kq);
            Ws[kq + 0][n] = v.x; Ws[kq + 1][n] = v.y;
            Ws[kq + 2][n] = v.z; Ws[kq + 3][n] = v.w;
        }
        __syncthreads();
        #pragma unroll
        for (int k = 0; k < GBK; k++) {
            float4 a0 = *(const float4*)&As[k][tm];
            float4 a1 = *(const float4*)&As[k][tm + 4];
            float4 bv = *(const float4*)&Ws[k][tn];
            float a[8] = {a0.x, a0.y, a0.z, a0.w, a1.x, a1.y, a1.z, a1.w};
            float bb[4] = {bv.x, bv.y, bv.z, bv.w};
            #pragma unroll
            for (int i = 0; i < 8; i++)
                #pragma unroll
                for (int j = 0; j < 4; j++) acc[i][j] += a[i] * bb[j];
        }
        __syncthreads();
    }

    if (Kc >= K) {
        #pragma unroll
        for (int i = 0; i < 8; i++) {
            int gm = bm + tm + i;
            #pragma unroll
            for (int j = 0; j < 4; j++) {
                int gn = bn + tn + j;
                if (gn < N) {
                    float v = acc[i][j] + bias[gn];
                    if (relu) v = fmaxf(v, 0.f);
                    C[(size_t)gm * N + gn] = v;
                }
            }
        }
    } else {
        float* Cp = C + (size_t)blockIdx.z * M * N;
        #pragma unroll
        for (int i = 0; i < 8; i++) {
            int gm = bm + tm + i;
            #pragma unroll
            for (int j = 0; j < 4; j++) {
                int gn = bn + tn + j;
                if (gn < N) Cp[(size_t)gm * N + gn] = acc[i][j];
            }
        }
    }
}

// ---------------- fc reduce + heads (warp-parallel heads) ----------------
__global__ __launch_bounds__(256) void k_fcredheads(const float* __restrict__ fcb,
                                                    const float* __restrict__ otw,
                                                    const float* __restrict__ otb,
                                                    const float* __restrict__ ctw,
                                                    const float* __restrict__ ctb) {
    __shared__ float sx[EMB];
    int b = blockIdx.x, tid = threadIdx.x;
    int lane = tid & 31, wid = tid >> 5;
    for (int i = tid; i < EMB; i += 256) {
        float s = fcb[i];
        #pragma unroll
        for (int p = 0; p < 7; p++) s += g_fcpart[p * Bsz * EMB + b * EMB + i];
        float v = fmaxf(s, 0.f);
        g_x[b * EMB + i] = v;
        sx[i] = v;
    }
    __syncthreads();
    #pragma unroll
    for (int j = 0; j < 6; j++) {
        int o = j * 8 + wid;
        if (o < 42) {
            const float* wp = (o < 40) ? (otw + o * EMB) : (ctw + (o - 40) * EMB);
            float s = 0.f;
            #pragma unroll
            for (int k = lane; k < EMB; k += 32) s += sx[k] * wp[k];
            #pragma unroll
            for (int d = 16; d > 0; d >>= 1) s += __shfl_xor_sync(0xFFFFFFFFu, s, d);
            if (lane == 0) {
                if (o < 40) g_ot[b * 40 + o] = s + otb[o];
                else        g_ct[b * 2 + (o - 40)] = s + ctb[o - 40];
            }
        }
    }
}

// ==== fused upsample + residual 3x3 conv, bf16 3-term, k16+k8, band=8, 512 thr ====
// Pixel record = 12 u32 (verified R13 layout). Band = 8 output rows (10-row tile,
// 8 staged source rows). Patches: 2 patch-rows x npx cols; warp w handles
// p = w, w+16, w+32.
__global__ __launch_bounds__(512, 1) void k_upconv_hmma4(
        const float* __restrict__ src, const float* __restrict__ w,
        const float* __restrict__ bias, float* __restrict__ out,
        int inS, int S, int Wp, int npx, float scale, int tileU, int auxU) {
    extern __shared__ uint32_t smu[];
    uint32_t* sHi = smu;
    uint32_t* sLo = smu + tileU;
    uint32_t* sAux = smu + 2 * tileU;        // raw staging then B fragments (5184)
    float* sRawF = (float*)sAux;
    float* sBias = (float*)(sAux + auxU);
    int tid = threadIdx.x, lane = tid & 31, wid = tid >> 5;
    int b = blockIdx.y, band = blockIdx.x;
    int y0 = band * 8;
    int g = lane >> 2, tg = lane & 3;

    // phase 0: stage raw src rows [ic][8][inS] + bias
    int sy0 = (int)(fmaxf((float)(y0 - 1), 0.f) * scale);
    const float* srcb = src + (size_t)b * 24 * inS * inS;
    int rawTot = 24 * 8 * inS;
    for (int e = tid; e < rawTot; e += 512) {
        int ic = e / (8 * inS);
        int r2 = e % (8 * inS);
        int ry = r2 / inS, x = r2 % inS;
        int sy = sy0 + ry;
        sRawF[e] = (sy < inS) ? srcb[(size_t)ic * inS * inS + sy * inS + x] : 0.f;
    }
    if (tid < 24) sBias[tid] = bias[tid];
    __syncthreads();

    // phase 1: bilinear upsample -> bf16 hi/lo 12-u32 records (10 tile rows)
    for (int pix = tid; pix < 10 * Wp; pix += 512) {
        int r = pix / Wp, c = pix - r * Wp;
        int gy = y0 + r - 1, gx = c - 1;
        uint32_t* rh = sHi + pix * 12;
        uint32_t* rl = sLo + pix * 12;
        float vb[24];
        if (gy >= 0 && gy < S && gx >= 0 && gx < S) {
            float py = gy * scale;
            int yl = min((int)py, inS - 2);
            float wy = py - (float)yl;
            float px = gx * scale;
            int xl = min((int)px, inS - 2);
            float wx = px - (float)xl;
            const float* base = sRawF + (yl - sy0) * inS + xl;
            #pragma unroll
            for (int ic = 0; ic < 24; ic++) {
                const float* rp = base + ic * (8 * inS);
                float v00 = rp[0], v01 = rp[1], v10 = rp[inS], v11 = rp[inS + 1];
                vb[ic] = (1.f - wy) * ((1.f - wx) * v00 + wx * v01) +
                         wy * ((1.f - wx) * v10 + wx * v11);
            }
        } else {
            #pragma unroll
            for (int ic = 0; ic < 24; ic++) vb[ic] = 0.f;
        }
        const int slotA[12] = {0, 2, 4, 6, 1, 3, 5, 7, 8, 9, 10, 11};
        #pragma unroll
        for (int j = 0; j < 12; j++) {
            uint32_t h = pack_bf16x2(vb[2 * j], vb[2 * j + 1]);
            float h0, h1;
            unpack_bf16x2(h, h0, h1);
            uint32_t l = pack_bf16x2(vb[2 * j] - h0, vb[2 * j + 1] - h1);
            rh[slotA[j]] = h;
            rl[slotA[j]] = l;
        }
    }
    __syncthreads();

    // phase 2: raw dead; build B fragments in sAux (5184 u32; verified layout)
    for (int e = tid; e < 5184; e += 512) {
        int tap = e / 576;
        int r = e % 576;
        int nt, hl, ic0, oc;
        if (r < 384) {
            int rr = r & 1; int q = r >> 1;
            int ln = q & 31; int hn = q >> 5;
            nt = hn % 3; hl = hn / 3;
            oc = nt * 8 + (ln >> 2);
            ic0 = 2 * (ln & 3) + 8 * rr;
        } else {
            int u = r - 384;
            int ln = u & 31; int hn = u >> 5;
            nt = hn % 3; hl = hn / 3;
            oc = nt * 8 + (ln >> 2);
            ic0 = 16 + 2 * (ln & 3);
        }
        float wv0 = w[(oc * 24 + ic0) * 9 + tap];
        float wv1 = w[(oc * 24 + ic0 + 1) * 9 + tap];
        float h0 = bf16f(wv0), h1 = bf16f(wv1);
        float v0 = hl ? (wv0 - h0) : h0;
        float v1 = hl ? (wv1 - h1) : h1;
        smu[2 * tileU + e] = pack_bf16x2(v0, v1);
    }
    __syncthreads();

    // phase 3: k-substep-outer, patch-inner (up to 3 patches per warp, 16 warps)
    const uint2* sHi2 = (const uint2*)sHi;
    const uint2* sLo2 = (const uint2*)sLo;
    int pr = g >> 2;
    int npatch = 2 * npx;
    int pix0[3]; bool pv[3]; int colb_[3]; int rowb_[3];
    #pragma unroll
    for (int pi = 0; pi < 3; pi++) {
        int p = wid + 16 * pi;
        pv[pi] = (p < npatch);
        int pp = pv[pi] ? p : 0;
        int pr2 = pp / npx, pcol = pp % npx;
        colb_[pi] = pcol * 4 + (g & 3);
        rowb_[pi] = pr2 * 4 + pr;
        pix0[pi] = rowb_[pi] * Wp + colb_[pi];
    }
    float acc[3][12];
    #pragma unroll
    for (int pi = 0; pi < 3; pi++)
        #pragma unroll
        for (int q = 0; q < 12; q++) acc[pi][q] = 0.f;

    #pragma unroll
    for (int ky = 0; ky < 3; ky++) {
        #pragma unroll
        for (int kx = 0; kx < 3; kx++) {
            int tap = ky * 3 + kx;
            const uint2* b16 = (const uint2*)(sAux + tap * 576);
            uint2 bh0 = b16[lane],       bh1 = b16[lane + 32],  bh2 = b16[lane + 64];
            uint2 bl0 = b16[lane + 96],  bl1 = b16[lane + 128], bl2 = b16[lane + 160];
            #pragma unroll
            for (int pi = 0; pi < 3; pi++) {
                if (!pv[pi]) continue;
                int pixA = pix0[pi] + ky * Wp + kx;
                int pixB = pixA + 2 * Wp;
                uint2 hA = sHi2[pixA * 6 + tg], hB = sHi2[pixB * 6 + tg];
                uint2 lA = sLo2[pixA * 6 + tg], lB = sLo2[pixB * 6 + tg];
                uint32_t ah[4] = {hA.x, hB.x, hA.y, hB.y};
                uint32_t al[4] = {lA.x, lB.x, lA.y, lB.y};
                mma_bf16(acc[pi] + 0, ah, bh0.x, bh0.y);
                mma_bf16(acc[pi] + 4, ah, bh1.x, bh1.y);
                mma_bf16(acc[pi] + 8, ah, bh2.x, bh2.y);
                mma_bf16(acc[pi] + 0, al, bh0.x, bh0.y);
                mma_bf16(acc[pi] + 4, al, bh1.x, bh1.y);
                mma_bf16(acc[pi] + 8, al, bh2.x, bh2.y);
                mma_bf16(acc[pi] + 0, ah, bl0.x, bl0.y);
                mma_bf16(acc[pi] + 4, ah, bl1.x, bl1.y);
                mma_bf16(acc[pi] + 8, ah, bl2.x, bl2.y);
            }
            const uint32_t* b8 = sAux + tap * 576 + 384;
            uint32_t c8h0 = b8[lane],      c8h1 = b8[lane + 32],  c8h2 = b8[lane + 64];
            uint32_t c8l0 = b8[lane + 96], c8l1 = b8[lane + 128], c8l2 = b8[lane + 160];
            #pragma unroll
            for (int pi = 0; pi < 3; pi++) {
                if (!pv[pi]) continue;
                int pixA = pix0[pi] + ky * Wp + kx;
                int pixB = pixA + 2 * Wp;
                uint32_t a0h = sHi[pixA * 12 + 8 + tg], a1h = sHi[pixB * 12 + 8 + tg];
                uint32_t a0l = sLo[pixA * 12 + 8 + tg], a1l = sLo[pixB * 12 + 8 + tg];
                mma_bf16_k8(acc[pi] + 0, a0h, a1h, c8h0);
                mma_bf16_k8(acc[pi] + 4, a0h, a1h, c8h1);
                mma_bf16_k8(acc[pi] + 8, a0h, a1h, c8h2);
                mma_bf16_k8(acc[pi] + 0, a0l, a1l, c8h0);
                mma_bf16_k8(acc[pi] + 4, a0l, a1l, c8h1);
                mma_bf16_k8(acc[pi] + 8, a0l, a1l, c8h2);
                mma_bf16_k8(acc[pi] + 0, a0h, a1h, c8l0);
                mma_bf16_k8(acc[pi] + 4, a0h, a1h, c8l1);
                mma_bf16_k8(acc[pi] + 8, a0h, a1h, c8l2);
            }
        }
    }

    // epilogue: residual reconstructed hi+lo, + bias, relu, masked stores
    float* ob = out + (size_t)b * 24 * S * S;
    #pragma unroll
    for (int pi = 0; pi < 3; pi++) {
        if (!pv[pi]) continue;
        int colb = colb_[pi];
        int gx = colb;
        int gy0 = y0 + rowb_[pi], gy1 = gy0 + 2;
        bool v0ok = (gy0 < S) && (gx < S);
        bool v1ok = (gy1 < S) && (gx < S);
        const uint32_t* ch0 = sHi + ((rowb_[pi] + 1) * Wp + colb + 1) * 12;
        const uint32_t* cl0 = sLo + ((rowb_[pi] + 1) * Wp + colb + 1) * 12;
        const uint32_t* ch1 = ch0 + 2 * Wp * 12;
        const uint32_t* cl1 = cl0 + 2 * Wp * 12;
        #pragma unroll
        for (int nt = 0; nt < 3; nt++) {
            const float* cp = acc[pi] + nt * 4;
            int oc = nt * 8 + 2 * tg;
            int j = nt * 4 + tg;
            int slot = (j < 8) ? (2 * (j & 3) + (j >> 2)) : j;
            float b0v = sBias[oc], b1v = sBias[oc + 1];
            if (v0ok) {
                float h0, h1, l0, l1;
                unpack_bf16x2(ch0[slot], h0, h1);
                unpack_bf16x2(cl0[slot], l0, l1);
                ob[((size_t)oc * S + gy0) * S + gx] =
                    fmaxf(cp[0] + h0 + l0 + b0v, 0.f);
                ob[((size_t)(oc + 1) * S + gy0) * S + gx] =
                    fmaxf(cp[1] + h1 + l1 + b1v, 0.f);
            }
            if (v1ok) {
                float h0, h1, l0, l1;
                unpack_bf16x2(ch1[slot], h0, h1);
                unpack_bf16x2(cl1[slot], l0, l1);
                ob[((size_t)oc * S + gy1) * S + gx] =
                    fmaxf(cp[2] + h0 + l0 + b0v, 0.f);
                ob[((size_t)(oc + 1) * S + gy1) * S + gx] =
                    fmaxf(cp[3] + h1 + l1 + b1v, 0.f);
            }
        }
    }
}

// ---------------- fused epilogue: 1x1 conv + sigmoid + flow + ct + grid + warp --------
__global__ __launch_bounds__(256) void k_final(const float* __restrict__ inp,
                                               const float* __restrict__ c3w,
                                               const float* __restrict__ c3b,
                                               float* __restrict__ outp) {
    __shared__ float s_w[KOBJ * 24];
    __shared__ float s_b[KOBJ];
    __shared__ float s_ot[KOBJ * 2];
    __shared__ float s_ct[2];
    int b = blockIdx.y, tid = threadIdx.x;
    int p = blockIdx.x * 256 + tid;
    for (int i = tid; i < KOBJ * 24; i += 256) s_w[i] = c3w[i];
    if (tid < KOBJ) s_b[tid] = c3b[tid];
    if (tid < KOBJ * 2) s_ot[tid] = g_ot[b * 40 + tid];
    if (tid < 2) s_ct[tid] = g_ct[b * 2 + tid];
    __syncthreads();
    if (p >= 7056) return;
    const float* mp = g_m84b + (size_t)b * 24 * 7056 + p;
    float mv[24];
    #pragma unroll
    for (int c = 0; c < 24; c++) mv[c] = mp[c * 7056];
    float fy = s_ct[0], fx = s_ct[1];
    #pragma unroll 4
    for (int k = 0; k < KOBJ; k++) {
        float s = s_b[k];
        #pragma unroll
        for (int c = 0; c < 24; c++) s += mv[c] * s_w[k * 24 + c];
        float mask = 1.f / (1.f + __expf(-s));
        fy += mask * s_ot[k * 2];
        fx += mask * s_ot[k * 2 + 1];
    }
    int gy = p / 84, gx = p % 84;
    const float isf = 0.01f * 84.0f;
    float ys = isf * fy + (float)gy;
    float xs = isf * fx + (float)gx;
    const float* src = inp + (size_t)b * 14112 + 7056;
    int x0 = min(max((int)floorf(xs), 0), 83);
    int y0 = min(max((int)floorf(ys), 0), 83);
    int x1 = min(x0 + 1, 83);
    int y1 = min(y0 + 1, 83);
    float Ia = src[y0 * 84 + x0], Ib = src[y1 * 84 + x0];
    float Ic = src[y0 * 84 + x1], Id = src[y1 * 84 + x1];
    float xc = fminf(fmaxf(xs, 0.f), 83.f);
    float yc = fminf(fmaxf(ys, 0.f), 83.f);
    float x0f = (float)x0, x1f = (float)x1, y0f = (float)y0, y1f = (float)y1;
    float o = (x1f - xc) * (y1f - yc) * Ia + (x1f - xc) * (yc - y0f) * Ib +
              (xc - x0f) * (y1f - yc) * Ic + (xc - x0f) * (yc - y0f) * Id;
    outp[(size_t)b * 7056 + p] = o;
}

// ---------------- launch ----------------
extern "C" void kernel_launch(void* const* d_in, const int* in_sizes, int n_in,
                              void* d_out, int out_size) {
    const float* inp = (const float*)d_in[0];
    const float* cw1 = (const float*)d_in[1];
    const float* cb1 = (const float*)d_in[2];
    const float* cw2 = (const float*)d_in[3];
    const float* cb2 = (const float*)d_in[4];
    const float* cw3 = (const float*)d_in[5];
    const float* cb3 = (const float*)d_in[6];
    const float* fcw = (const float*)d_in[7];
    const float* fcb = (const float*)d_in[8];
    const float* otw = (const float*)d_in[9];
    const float* otb = (const float*)d_in[10];
    const float* ctw = (const float*)d_in[11];
    const float* ctb = (const float*)d_in[12];
    const float* m1w = (const float*)d_in[13];
    const float* m1b = (const float*)d_in[14];
    const float* c1w = (const float*)d_in[15];
    const float* c1b = (const float*)d_in[16];
    const float* c2w = (const float*)d_in[17];
    const float* c2b = (const float*)d_in[18];
    const float* c3w = (const float*)d_in[19];
    const float* c3b = (const float*)d_in[20];
    float* outp = (float*)d_out;

    cudaFuncSetAttribute(k_conv1,  cudaFuncAttributeMaxDynamicSharedMemorySize, 72832);
    cudaFuncSetAttribute(k_conv23, cudaFuncAttributeMaxDynamicSharedMemorySize, 168192);
    cudaFuncSetAttribute(k_upconv_hmma4, cudaFuncAttributeMaxDynamicSharedMemorySize, 114912);

    float *p_h3, *p_x, *p_fcpart, *p_m21, *p_m42b, *p_m84b;
    cudaGetSymbolAddress((void**)&p_h3,     g_h3);
    cudaGetSymbolAddress((void**)&p_x,      g_x);
    cudaGetSymbolAddress((void**)&p_fcpart, g_fcpart);
    cudaGetSymbolAddress((void**)&p_m21,    g_m21);
    cudaGetSymbolAddress((void**)&p_m42b,   g_m42b);
    cudaGetSymbolAddress((void**)&p_m84b,   g_m84b);

    // encoder
    k_conv1<<<Bsz, 256, 72832>>>(inp, cw1, cb1);
    k_conv23<<<Bsz, 256, 168192>>>(cw2, cb2, cw3, cb3);
    // fc: split-K=7 + fused reduce(relu)+heads
    k_gemm2<<<dim3(EMB / GBN, Bsz / GBM, 7), 256>>>(p_h3, fcw, fcb, p_fcpart,
                                                    Bsz, EMB, 3136, 448, 0);
    k_fcredheads<<<Bsz, 256>>>(fcb, otw, otb, ctw, ctb);
    // mask fc
    k_gemm2<<<dim3((10584 + GBN - 1) / GBN, Bsz / GBM, 1), 256>>>(p_x, m1w, m1b, p_m21,
                                                                  Bsz, 10584, EMB, EMB, 0);
    // decoder: band=8, 512 threads
    // conv42: Wp=46, tileU=10*46*12=5520, auxU=max(24*8*21=4032,5184)=5184
    //   smem=(2*5520+5184+24)*4=65952, bands=6, npx=11
    k_upconv_hmma4<<<dim3(6, Bsz), 512, 65952>>>(p_m21, c1w, c1b, p_m42b,
                                                 21, 42, 46, 11, 20.f / 41.f,
                                                 5520, 5184);
    // conv84: Wp=86, tileU=10*86*12=10320, auxU=max(24*8*42=8064,5184)=8064
    //   smem=(2*10320+8064+24)*4=114912, bands=11, npx=21
    k_upconv_hmma4<<<dim3(11, Bsz), 512, 114912>>>(p_m42b, c2w, c2b, p_m84b,
                                                   42, 84, 86, 21, 41.f / 83.f,
                                                   10320, 8064);
    // fused: 1x1 conv + sigmoid masks + flow + warp
    k_final<<<dim3(28, Bsz), 256>>>(inp, c3w, c3b, outp);
    (void)in_sizes; (void)n_in; (void)out_size;
}

// round 15
// speedup vs baseline: 1.8095x; 1.0234x over previous
#include <cuda_runtime.h>
#include <cuda_bf16.h>
#include <math.h>
#include <stdint.h>

#define Bsz 512
#define HH 84
#define WW 84
#define KOBJ 20
#define DEPTH 24
#define EMB 512
#define M1N 10584

// ---------------- scratch (static device globals; no allocations) ----------------
__device__ float g_h1[Bsz * 32 * 20 * 20];
__device__ float g_h3[Bsz * 64 * 7 * 7];
__device__ float g_fcpart[7 * Bsz * EMB];
__device__ float g_x [Bsz * EMB];
__device__ float g_ot[Bsz * KOBJ * 2];
__device__ float g_ct[Bsz * 2];
__device__ float g_m21 [Bsz * DEPTH * 21 * 21];
__device__ float g_m42b[Bsz * DEPTH * 42 * 42];
__device__ float g_m84b[Bsz * DEPTH * 84 * 84];
// packed bf16 hi/lo fragment operands for the m1 HMMA GEMM
__device__ uint32_t g_m1whi[M1N * 256];
__device__ uint32_t g_m1wlo[M1N * 256];
__device__ uint32_t g_xhi[Bsz * 256];
__device__ uint32_t g_xlo[Bsz * 256];

// ---------------- helpers ----------------
__device__ __forceinline__ uint32_t pack_bf16x2(float lo, float hi) {
    uint32_t r;
    asm("cvt.rn.bf16x2.f32 %0, %1, %2;" : "=r"(r) : "f"(hi), "f"(lo));
    return r;  // low16 = bf16(lo), high16 = bf16(hi)
}
__device__ __forceinline__ void unpack_bf16x2(uint32_t u, float& lo, float& hi) {
    lo = __uint_as_float(u << 16);
    hi = __uint_as_float(u & 0xFFFF0000u);
}
__device__ __forceinline__ float bf16f(float v) {
    return __bfloat162float(__float2bfloat16(v));
}
__device__ __forceinline__ void mma_bf16(float c[4], const uint32_t a[4],
                                         uint32_t b0, uint32_t b1) {
    asm volatile("mma.sync.aligned.m16n8k16.row.col.f32.bf16.bf16.f32 "
        "{%0,%1,%2,%3}, {%4,%5,%6,%7}, {%8,%9}, {%0,%1,%2,%3};"
        : "+f"(c[0]), "+f"(c[1]), "+f"(c[2]), "+f"(c[3])
        : "r"(a[0]), "r"(a[1]), "r"(a[2]), "r"(a[3]), "r"(b0), "r"(b1));
}
__device__ __forceinline__ void mma_bf16_k8(float c[4], uint32_t a0, uint32_t a1,
                                            uint32_t b0) {
    asm volatile("mma.sync.aligned.m16n8k8.row.col.f32.bf16.bf16.f32 "
        "{%0,%1,%2,%3}, {%4,%5}, {%6}, {%0,%1,%2,%3};"
        : "+f"(c[0]), "+f"(c[1]), "+f"(c[2]), "+f"(c[3])
        : "r"(a0), "r"(a1), "r"(b0));
}

// ---------------- pack W (m1w) into hi/lo fragment layout ----------------
// pair j of row n -> index n*256 + (j>>3)*8 + slot(j&7), slot = {0,2,4,6,1,3,5,7}
__global__ __launch_bounds__(256) void k_packW(const float* __restrict__ w) {
    int e = blockIdx.x * 256 + threadIdx.x;
    if (e >= M1N * 256) return;
    int n = e >> 8, j = e & 255;
    int s = j >> 3, jj = j & 7;
    int slot = (jj < 4) ? (2 * jj) : (2 * (jj - 4) + 1);
    const float* wp = w + (size_t)n * 512 + 2 * j;
    float w0 = wp[0], w1 = wp[1];
    float h0 = bf16f(w0), h1 = bf16f(w1);
    int idx = n * 256 + s * 8 + slot;
    g_m1whi[idx] = pack_bf16x2(h0, h1);
    g_m1wlo[idx] = pack_bf16x2(w0 - h0, w1 - h1);
}

// ---------------- pack A (g_x) into hi/lo fragment layout ----------------
__global__ __launch_bounds__(256) void k_packA() {
    int e = blockIdx.x * 256 + threadIdx.x;
    if (e >= Bsz * 256) return;
    int m = e >> 8, j = e & 255;
    int s = j >> 3, jj = j & 7;
    int slot = (jj < 4) ? (2 * jj) : (2 * (jj - 4) + 1);
    const float* xp = g_x + (size_t)m * 512 + 2 * j;
    float x0 = xp[0], x1 = xp[1];
    float h0 = bf16f(x0), h1 = bf16f(x1);
    int idx = m * 256 + s * 8 + slot;
    g_xhi[idx] = pack_bf16x2(h0, h1);
    g_xlo[idx] = pack_bf16x2(x0 - h0, x1 - h1);
}

// ---------------- m1 GEMM via bf16 3-term HMMA: C[512,10584] = x @ W^T + b ------
__global__ __launch_bounds__(256) void k_gemmhmma(const float* __restrict__ bias,
                                                  float* __restrict__ C) {
    int tid = threadIdx.x, lane = tid & 31, wid = tid >> 5;
    int g = lane >> 2, tg = lane & 3;
    int bn = blockIdx.x * 64, bm = blockIdx.y * 128;
    int nw = wid & 3, mw = wid >> 2;
    int m0 = bm + mw * 64, n0 = bn + nw * 16;
    const uint2* Ahi = (const uint2*)g_xhi;
    const uint2* Alo = (const uint2*)g_xlo;
    const uint2* Whi = (const uint2*)g_m1whi;
    const uint2* Wlo = (const uint2*)g_m1wlo;
    float acc[4][2][4];
    #pragma unroll
    for (int t = 0; t < 4; t++)
        #pragma unroll
        for (int u = 0; u < 2; u++)
            #pragma unroll
            for (int q = 0; q < 4; q++) acc[t][u][q] = 0.f;

    int nidx[2];
    #pragma unroll
    for (int u = 0; u < 2; u++) {
        int n = n0 + 8 * u + g;
        nidx[u] = (n < M1N) ? n : (M1N - 1);   // clamp (stores guarded)
    }

    #pragma unroll 4
    for (int s = 0; s < 32; s++) {
        uint2 wh[2], wl[2];
        #pragma unroll
        for (int u = 0; u < 2; u++) {
            wh[u] = Whi[nidx[u] * 128 + s * 4 + tg];
            wl[u] = Wlo[nidx[u] * 128 + s * 4 + tg];
        }
        #pragma unroll
        for (int t = 0; t < 4; t++) {
            int rA = m0 + 16 * t + g;
            uint2 hA = Ahi[rA * 128 + s * 4 + tg];
            uint2 hB = Ahi[(rA + 8) * 128 + s * 4 + tg];
            uint2 lA = Alo[rA * 128 + s * 4 + tg];
            uint2 lB = Alo[(rA + 8) * 128 + s * 4 + tg];
            uint32_t ah[4] = {hA.x, hB.x, hA.y, hB.y};
            uint32_t al[4] = {lA.x, lB.x, lA.y, lB.y};
            #pragma unroll
            for (int u = 0; u < 2; u++) {
                mma_bf16(acc[t][u], ah, wh[u].x, wh[u].y);
                mma_bf16(acc[t][u], al, wh[u].x, wh[u].y);
                mma_bf16(acc[t][u], ah, wl[u].x, wl[u].y);
            }
        }
    }

    #pragma unroll
    for (int t = 0; t < 4; t++) {
        int row = m0 + 16 * t + g;
        #pragma unroll
        for (int u = 0; u < 2; u++) {
            int c = n0 + 8 * u + 2 * tg;
            if (c < M1N) {
                float b0 = bias[c], b1 = bias[c + 1];
                C[(size_t)row * M1N + c]           = acc[t][u][0] + b0;
                C[(size_t)row * M1N + c + 1]       = acc[t][u][1] + b1;
                C[(size_t)(row + 8) * M1N + c]     = acc[t][u][2] + b0;
                C[(size_t)(row + 8) * M1N + c + 1] = acc[t][u][3] + b1;
            }
        }
    }
}

// ---------------- conv1: [B,2,84,84] k8 s4 -> [B,32,20,20], relu ----------------
__global__ __launch_bounds__(256) void k_conv1(const float* __restrict__ inp,
                                               const float* __restrict__ w,
                                               const float* __restrict__ bias) {
    extern __shared__ float sm[];
    float* sIn = sm;          // 14112
    float* sW  = sm + 14112;  // 4096
    int b = blockIdx.x, tid = threadIdx.x;
    const float* ip = inp + b * 14112;
    for (int i = tid; i < 14112; i += 256) sIn[i] = ip[i];
    for (int i = tid; i < 4096;  i += 256) sW[i]  = w[i];
    __syncthreads();
    for (int o = tid; o < 3200; o += 256) {
        int oc = o / 100; int r = o % 100;
        int oy = (r / 10) * 2, ox = (r % 10) * 2;
        float a00 = 0.f, a01 = 0.f, a10 = 0.f, a11 = 0.f;
        for (int ic = 0; ic < 2; ic++) {
            const float* wp  = sW + (oc * 2 + ic) * 64;
            const float* inb = sIn + ic * 7056;
            #pragma unroll
            for (int ky = 0; ky < 8; ky++) {
                const float* r0 = inb + (oy * 4 + ky) * 84 + ox * 4;
                const float* r1 = r0 + 4 * 84;
                float v0[12], v1[12];
                #pragma unroll
                for (int j = 0; j < 12; j++) { v0[j] = r0[j]; v1[j] = r1[j]; }
                #pragma unroll
                for (int kx = 0; kx < 8; kx++) {
                    float ww = wp[ky * 8 + kx];
                    a00 += v0[kx] * ww;  a01 += v0[kx + 4] * ww;
                    a10 += v1[kx] * ww;  a11 += v1[kx + 4] * ww;
                }
            }
        }
        float bb = bias[oc];
        float* op = g_h1 + b * 12800 + oc * 400 + oy * 20 + ox;
        op[0]  = fmaxf(a00 + bb, 0.f); op[1]  = fmaxf(a01 + bb, 0.f);
        op[20] = fmaxf(a10 + bb, 0.f); op[21] = fmaxf(a11 + bb, 0.f);
    }
}

// ---------------- conv2+conv3 fused (h2 stays in smem) ----------------
__global__ __launch_bounds__(256) void k_conv23(const float* __restrict__ w2,
                                                const float* __restrict__ b2,
                                                const float* __restrict__ w3,
                                                const float* __restrict__ b3) {
    extern __shared__ float sm[];
    float* sIn1 = sm;
    float* sW2  = sm + 12800;
    float* sH2  = sm + 36864;
    int b = blockIdx.x, tid = threadIdx.x;
    const float* ip = g_h1 + b * 12800;
    for (int i = tid; i < 12800; i += 256) sIn1[i] = ip[i];
    for (int ch = 0; ch < 2; ch++) {
        __syncthreads();
        for (int i = tid; i < 16384; i += 256) sW2[i] = w2[ch * 16384 + i];
        __syncthreads();
        if (tid < 216) {
            int ocg = tid / 27; int r = tid % 27; int oy = r / 3; int oxg = (r % 3) * 3;
            float acc[4][3] = {};
            int iy0 = oy * 2, ix0 = oxg * 2;
            for (int ic = 0; ic < 32; ic++) {
                #pragma unroll
                for (int ky = 0; ky < 4; ky++) {
                    const float* rp = sIn1 + ic * 400 + (iy0 + ky) * 20 + ix0;
                    float v[8];
                    #pragma unroll
                    for (int j = 0; j < 8; j++) v[j] = rp[j];
                    #pragma unroll
                    for (int u = 0; u < 4; u++) {
                        const float* wp = sW2 + ((ocg * 4 + u) * 32 + ic) * 16 + ky * 4;
                        #pragma unroll
                        for (int kx = 0; kx < 4; kx++) {
                            float ww = wp[kx];
                            acc[u][0] += v[kx] * ww;
                            acc[u][1] += v[kx + 2] * ww;
                            acc[u][2] += v[kx + 4] * ww;
                        }
                    }
                }
            }
            #pragma unroll
            for (int u = 0; u < 4; u++) {
                int oc = ch * 32 + ocg * 4 + u;
                float bb = b2[oc];
                float* op = sH2 + oc * 81 + oy * 9 + oxg;
                #pragma unroll
                for (int j = 0; j < 3; j++) op[j] = fmaxf(acc[u][j] + bb, 0.f);
            }
        }
    }
    __syncthreads();
    for (int i = tid; i < 36864; i += 256) sm[i] = w3[i];
    __syncthreads();
    for (int it = tid; it < 448; it += 256) {
        int oc = it / 7, oy = it % 7;
        float acc[7] = {};
        for (int ic = 0; ic < 64; ic++) {
            const float* wp = sm + (oc * 64 + ic) * 9;
            #pragma unroll
            for (int ky = 0; ky < 3; ky++) {
                const float* rp = sH2 + ic * 81 + (oy + ky) * 9;
                float v[9];
                #pragma unroll
                for (int j = 0; j < 9; j++) v[j] = rp[j];
                #pragma unroll
                for (int kx = 0; kx < 3; kx++) {
                    float ww = wp[ky * 3 + kx];
                    #pragma unroll
                    for (int j = 0; j < 7; j++) acc[j] += v[j + kx] * ww;
                }
            }
        }
        float bb = b3[oc];
        float* op = g_h3 + b * 3136 + oc * 49 + oy * 7;
        #pragma unroll
        for (int j = 0; j < 7; j++) op[j] = fmaxf(acc[j] + bb, 0.f);
    }
}

// ---------------- GEMM v2 (fc only now) ----------------
#define GBM 128
#define GBN 64
#define GBK 16
__global__ __launch_bounds__(256) void k_gemm2(const float* __restrict__ A,
                                               const float* __restrict__ W,
                                               const float* __restrict__ bias,
                                               float* __restrict__ C,
                                               int M, int N, int K, int Kc, int relu) {
    __shared__ float As[GBK][GBM];
    __shared__ float Ws[GBK][GBN];
    int bm = blockIdx.y * GBM, bn = blockIdx.x * GBN;
    int ks = blockIdx.z * Kc;
    int ke = min(ks + Kc, K);
    int tid = threadIdx.x;
    float acc[8][4];
    #pragma unroll
    for (int i = 0; i < 8; i++)
        #pragma unroll
        for (int j = 0; j < 4; j++) acc[i][j] = 0.f;

    int tm = (tid / 16) * 8, tn = (tid % 16) * 4;

    for (int k0 = ks; k0 < ke; k0 += GBK) {
        #pragma unroll
        for (int l = tid; l < 512; l += 256) {
            int m = l >> 2, kq = (l & 3) << 2;
            float4 v = *(const float4*)(A + (size_t)(bm + m) * K + k0 + kq);
            As[kq + 0][m] = v.x; As[kq + 1][m] = v.y;
            As[kq + 2][m] = v.z; As[kq + 3][m] = v.w;
        }
        {
            int n = tid >> 2, kq = (tid & 3) << 2;
            int gn = bn + n;
            float4 v = make_float4(0.f, 0.f, 0.f, 0.f);
            if (gn < N) v = *(const float4*)(W + (size_t)gn * K + k0 + kq);
            Ws[kq + 0][n] = v.x; Ws[kq + 1][n] = v.y;
            Ws[kq + 2][n] = v.z; Ws[kq + 3][n] = v.w;
        }
        __syncthreads();
        #pragma unroll
        for (int k = 0; k < GBK; k++) {
            float4 a0 = *(const float4*)&As[k][tm];
            float4 a1 = *(const float4*)&As[k][tm + 4];
            float4 bv = *(const float4*)&Ws[k][tn];
            float a[8] = {a0.x, a0.y, a0.z, a0.w, a1.x, a1.y, a1.z, a1.w};
            float bb[4] = {bv.x, bv.y, bv.z, bv.w};
            #pragma unroll
            for (int i = 0; i < 8; i++)
                #pragma unroll
                for (int j = 0; j < 4; j++) acc[i][j] += a[i] * bb[j];
        }
        __syncthreads();
    }

    if (Kc >= K) {
        #pragma unroll
        for (int i = 0; i < 8; i++) {
            int gm = bm + tm + i;
            #pragma unroll
            for (int j = 0; j < 4; j++) {
                int gn = bn + tn + j;
                if (gn < N) {
                    float v = acc[i][j] + bias[gn];
                    if (relu) v = fmaxf(v, 0.f);
                    C[(size_t)gm * N + gn] = v;
                }
            }
        }
    } else {
        float* Cp = C + (size_t)blockIdx.z * M * N;
        #pragma unroll
        for (int i = 0; i < 8; i++) {
            int gm = bm + tm + i;
            #pragma unroll
            for (int j = 0; j < 4; j++) {
                int gn = bn + tn + j;
                if (gn < N) Cp[(size_t)gm * N + gn] = acc[i][j];
            }
        }
    }
}

// ---------------- fc reduce + heads (warp-parallel heads) ----------------
__global__ __launch_bounds__(256) void k_fcredheads(const float* __restrict__ fcb,
                                                    const float* __restrict__ otw,
                                                    const float* __restrict__ otb,
                                                    const float* __restrict__ ctw,
                                                    const float* __restrict__ ctb) {
    __shared__ float sx[EMB];
    int b = blockIdx.x, tid = threadIdx.x;
    int lane = tid & 31, wid = tid >> 5;
    for (int i = tid; i < EMB; i += 256) {
        float s = fcb[i];
        #pragma unroll
        for (int p = 0; p < 7; p++) s += g_fcpart[p * Bsz * EMB + b * EMB + i];
        float v = fmaxf(s, 0.f);
        g_x[b * EMB + i] = v;
        sx[i] = v;
    }
    __syncthreads();
    #pragma unroll
    for (int j = 0; j < 6; j++) {
        int o = j * 8 + wid;
        if (o < 42) {
            const float* wp = (o < 40) ? (otw + o * EMB) : (ctw + (o - 40) * EMB);
            float s = 0.f;
            #pragma unroll
            for (int k = lane; k < EMB; k += 32) s += sx[k] * wp[k];
            #pragma unroll
            for (int d = 16; d > 0; d >>= 1) s += __shfl_xor_sync(0xFFFFFFFFu, s, d);
            if (lane == 0) {
                if (o < 40) g_ot[b * 40 + o] = s + otb[o];
                else        g_ct[b * 2 + (o - 40)] = s + ctb[o - 40];
            }
        }
    }
}

// ==== fused upsample + residual 3x3 conv, bf16 3-term, k16+k8, band=8, 512 thr ====
__global__ __launch_bounds__(512, 1) void k_upconv_hmma4(
        const float* __restrict__ src, const float* __restrict__ w,
        const float* __restrict__ bias, float* __restrict__ out,
        int inS, int S, int Wp, int npx, float scale, int tileU, int auxU) {
    extern __shared__ uint32_t smu[];
    uint32_t* sHi = smu;
    uint32_t* sLo = smu + tileU;
    uint32_t* sAux = smu + 2 * tileU;        // raw staging then B fragments (5184)
    float* sRawF = (float*)sAux;
    float* sBias = (float*)(sAux + auxU);
    int tid = threadIdx.x, lane = tid & 31, wid = tid >> 5;
    int b = blockIdx.y, band = blockIdx.x;
    int y0 = band * 8;
    int g = lane >> 2, tg = lane & 3;

    // phase 0: stage raw src rows [ic][8][inS] + bias
    int sy0 = (int)(fmaxf((float)(y0 - 1), 0.f) * scale);
    const float* srcb = src + (size_t)b * 24 * inS * inS;
    int rawTot = 24 * 8 * inS;
    for (int e = tid; e < rawTot; e += 512) {
        int ic = e / (8 * inS);
        int r2 = e % (8 * inS);
        int ry = r2 / inS, x = r2 % inS;
        int sy = sy0 + ry;
        sRawF[e] = (sy < inS) ? srcb[(size_t)ic * inS * inS + sy * inS + x] : 0.f;
    }
    if (tid < 24) sBias[tid] = bias[tid];
    __syncthreads();

    // phase 1: bilinear upsample -> bf16 hi/lo 12-u32 records (10 tile rows)
    for (int pix = tid; pix < 10 * Wp; pix += 512) {
        int r = pix / Wp, c = pix - r * Wp;
        int gy = y0 + r - 1, gx = c - 1;
        uint32_t* rh = sHi + pix * 12;
        uint32_t* rl = sLo + pix * 12;
        float vb[24];
        if (gy >= 0 && gy < S && gx >= 0 && gx < S) {
            float py = gy * scale;
            int yl = min((int)py, inS - 2);
            float wy = py - (float)yl;
            float px = gx * scale;
            int xl = min((int)px, inS - 2);
            float wx = px - (float)xl;
            const float* base = sRawF + (yl - sy0) * inS + xl;
            #pragma unroll
            for (int ic = 0; ic < 24; ic++) {
                const float* rp = base + ic * (8 * inS);
                float v00 = rp[0], v01 = rp[1], v10 = rp[inS], v11 = rp[inS + 1];
                vb[ic] = (1.f - wy) * ((1.f - wx) * v00 + wx * v01) +
                         wy * ((1.f - wx) * v10 + wx * v11);
            }
        } else {
            #pragma unroll
            for (int ic = 0; ic < 24; ic++) vb[ic] = 0.f;
        }
        const int slotA[12] = {0, 2, 4, 6, 1, 3, 5, 7, 8, 9, 10, 11};
        #pragma unroll
        for (int j = 0; j < 12; j++) {
            uint32_t h = pack_bf16x2(vb[2 * j], vb[2 * j + 1]);
            float h0, h1;
            unpack_bf16x2(h, h0, h1);
            uint32_t l = pack_bf16x2(vb[2 * j] - h0, vb[2 * j + 1] - h1);
            rh[slotA[j]] = h;
            rl[slotA[j]] = l;
        }
    }
    __syncthreads();

    // phase 2: raw dead; build B fragments in sAux (5184 u32; verified layout)
    for (int e = tid; e < 5184; e += 512) {
        int tap = e / 576;
        int r = e % 576;
        int nt, hl, ic0, oc;
        if (r < 384) {
            int rr = r & 1; int q = r >> 1;
            int ln = q & 31; int hn = q >> 5;
            nt = hn % 3; hl = hn / 3;
            oc = nt * 8 + (ln >> 2);
            ic0 = 2 * (ln & 3) + 8 * rr;
        } else {
            int u = r - 384;
            int ln = u & 31; int hn = u >> 5;
            nt = hn % 3; hl = hn / 3;
            oc = nt * 8 + (ln >> 2);
            ic0 = 16 + 2 * (ln & 3);
        }
        float wv0 = w[(oc * 24 + ic0) * 9 + tap];
        float wv1 = w[(oc * 24 + ic0 + 1) * 9 + tap];
        float h0 = bf16f(wv0), h1 = bf16f(wv1);
        float v0 = hl ? (wv0 - h0) : h0;
        float v1 = hl ? (wv1 - h1) : h1;
        smu[2 * tileU + e] = pack_bf16x2(v0, v1);
    }
    __syncthreads();

    // phase 3: k-substep-outer, patch-inner (up to 3 patches per warp, 16 warps)
    const uint2* sHi2 = (const uint2*)sHi;
    const uint2* sLo2 = (const uint2*)sLo;
    int pr = g >> 2;
    int npatch = 2 * npx;
    int pix0[3]; bool pv[3]; int colb_[3]; int rowb_[3];
    #pragma unroll
    for (int pi = 0; pi < 3; pi++) {
        int p = wid + 16 * pi;
        pv[pi] = (p < npatch);
        int pp = pv[pi] ? p : 0;
        int pr2 = pp / npx, pcol = pp % npx;
        colb_[pi] = pcol * 4 + (g & 3);
        rowb_[pi] = pr2 * 4 + pr;
        pix0[pi] = rowb_[pi] * Wp + colb_[pi];
    }
    float acc[3][12];
    #pragma unroll
    for (int pi = 0; pi < 3; pi++)
        #pragma unroll
        for (int q = 0; q < 12; q++) acc[pi][q] = 0.f;

    #pragma unroll
    for (int ky = 0; ky < 3; ky++) {
        #pragma unroll
        for (int kx = 0; kx < 3; kx++) {
            int tap = ky * 3 + kx;
            const uint2* b16 = (const uint2*)(sAux + tap * 576);
            uint2 bh0 = b16[lane],       bh1 = b16[lane + 32],  bh2 = b16[lane + 64];
            uint2 bl0 = b16[lane + 96],  bl1 = b16[lane + 128], bl2 = b16[lane + 160];
            #pragma unroll
            for (int pi = 0; pi < 3; pi++) {
                if (!pv[pi]) continue;
                int pixA = pix0[pi] + ky * Wp + kx;
                int pixB = pixA + 2 * Wp;
                uint2 hA = sHi2[pixA * 6 + tg], hB = sHi2[pixB * 6 + tg];
                uint2 lA = sLo2[pixA * 6 + tg], lB = sLo2[pixB * 6 + tg];
                uint32_t ah[4] = {hA.x, hB.x, hA.y, hB.y};
                uint32_t al[4] = {lA.x, lB.x, lA.y, lB.y};
                mma_bf16(acc[pi] + 0, ah, bh0.x, bh0.y);
                mma_bf16(acc[pi] + 4, ah, bh1.x, bh1.y);
                mma_bf16(acc[pi] + 8, ah, bh2.x, bh2.y);
                mma_bf16(acc[pi] + 0, al, bh0.x, bh0.y);
                mma_bf16(acc[pi] + 4, al, bh1.x, bh1.y);
                mma_bf16(acc[pi] + 8, al, bh2.x, bh2.y);
                mma_bf16(acc[pi] + 0, ah, bl0.x, bl0.y);
                mma_bf16(acc[pi] + 4, ah, bl1.x, bl1.y);
                mma_bf16(acc[pi] + 8, ah, bl2.x, bl2.y);
            }
            const uint32_t* b8 = sAux + tap * 576 + 384;
            uint32_t c8h0 = b8[lane],      c8h1 = b8[lane + 32],  c8h2 = b8[lane + 64];
            uint32_t c8l0 = b8[lane + 96], c8l1 = b8[lane + 128], c8l2 = b8[lane + 160];
            #pragma unroll
            for (int pi = 0; pi < 3; pi++) {
                if (!pv[pi]) continue;
                int pixA = pix0[pi] + ky * Wp + kx;
                int pixB = pixA + 2 * Wp;
                uint32_t a0h = sHi[pixA * 12 + 8 + tg], a1h = sHi[pixB * 12 + 8 + tg];
                uint32_t a0l = sLo[pixA * 12 + 8 + tg], a1l = sLo[pixB * 12 + 8 + tg];
                mma_bf16_k8(acc[pi] + 0, a0h, a1h, c8h0);
                mma_bf16_k8(acc[pi] + 4, a0h, a1h, c8h1);
                mma_bf16_k8(acc[pi] + 8, a0h, a1h, c8h2);
                mma_bf16_k8(acc[pi] + 0, a0l, a1l, c8h0);
                mma_bf16_k8(acc[pi] + 4, a0l, a1l, c8h1);
                mma_bf16_k8(acc[pi] + 8, a0l, a1l, c8h2);
                mma_bf16_k8(acc[pi] + 0, a0h, a1h, c8l0);
                mma_bf16_k8(acc[pi] + 4, a0h, a1h, c8l1);
                mma_bf16_k8(acc[pi] + 8, a0h, a1h, c8l2);
            }
        }
    }

    // epilogue: residual reconstructed hi+lo, + bias, relu, masked stores
    float* ob = out + (size_t)b * 24 * S * S;
    #pragma unroll
    for (int pi = 0; pi < 3; pi++) {
        if (!pv[pi]) continue;
        int colb = colb_[pi];
        int gx = colb;
        int gy0 = y0 + rowb_[pi], gy1 = gy0 + 2;
        bool v0ok = (gy0 < S) && (gx < S);
        bool v1ok = (gy1 < S) && (gx < S);
        const uint32_t* ch0 = sHi + ((rowb_[pi] + 1) * Wp + colb + 1) * 12;
        const uint32_t* cl0 = sLo + ((rowb_[pi] + 1) * Wp + colb + 1) * 12;
        const uint32_t* ch1 = ch0 + 2 * Wp * 12;
        const uint32_t* cl1 = cl0 + 2 * Wp * 12;
        #pragma unroll
        for (int nt = 0; nt < 3; nt++) {
            const float* cp = acc[pi] + nt * 4;
            int oc = nt * 8 + 2 * tg;
            int j = nt * 4 + tg;
            int slot = (j < 8) ? (2 * (j & 3) + (j >> 2)) : j;
            float b0v = sBias[oc], b1v = sBias[oc + 1];
            if (v0ok) {
                float h0, h1, l0, l1;
                unpack_bf16x2(ch0[slot], h0, h1);
                unpack_bf16x2(cl0[slot], l0, l1);
                ob[((size_t)oc * S + gy0) * S + gx] =
                    fmaxf(cp[0] + h0 + l0 + b0v, 0.f);
                ob[((size_t)(oc + 1) * S + gy0) * S + gx] =
                    fmaxf(cp[1] + h1 + l1 + b1v, 0.f);
            }
            if (v1ok) {
                float h0, h1, l0, l1;
                unpack_bf16x2(ch1[slot], h0, h1);
                unpack_bf16x2(cl1[slot], l0, l1);
                ob[((size_t)oc * S + gy1) * S + gx] =
                    fmaxf(cp[2] + h0 + l0 + b0v, 0.f);
                ob[((size_t)(oc + 1) * S + gy1) * S + gx] =
                    fmaxf(cp[3] + h1 + l1 + b1v, 0.f);
            }
        }
    }
}

// ---------------- fused epilogue: 1x1 conv + sigmoid + flow + ct + grid + warp --------
__global__ __launch_bounds__(256) void k_final(const float* __restrict__ inp,
                                               const float* __restrict__ c3w,
                                               const float* __restrict__ c3b,
                                               float* __restrict__ outp) {
    __shared__ float s_w[KOBJ * 24];
    __shared__ float s_b[KOBJ];
    __shared__ float s_ot[KOBJ * 2];
    __shared__ float s_ct[2];
    int b = blockIdx.y, tid = threadIdx.x;
    int p = blockIdx.x * 256 + tid;
    for (int i = tid; i < KOBJ * 24; i += 256) s_w[i] = c3w[i];
    if (tid < KOBJ) s_b[tid] = c3b[tid];
    if (tid < KOBJ * 2) s_ot[tid] = g_ot[b * 40 + tid];
    if (tid < 2) s_ct[tid] = g_ct[b * 2 + tid];
    __syncthreads();
    if (p >= 7056) return;
    const float* mp = g_m84b + (size_t)b * 24 * 7056 + p;
    float mv[24];
    #pragma unroll
    for (int c = 0; c < 24; c++) mv[c] = mp[c * 7056];
    float fy = s_ct[0], fx = s_ct[1];
    #pragma unroll 4
    for (int k = 0; k < KOBJ; k++) {
        float s = s_b[k];
        #pragma unroll
        for (int c = 0; c < 24; c++) s += mv[c] * s_w[k * 24 + c];
        float mask = 1.f / (1.f + __expf(-s));
        fy += mask * s_ot[k * 2];
        fx += mask * s_ot[k * 2 + 1];
    }
    int gy = p / 84, gx = p % 84;
    const float isf = 0.01f * 84.0f;
    float ys = isf * fy + (float)gy;
    float xs = isf * fx + (float)gx;
    const float* src = inp + (size_t)b * 14112 + 7056;
    int x0 = min(max((int)floorf(xs), 0), 83);
    int y0 = min(max((int)floorf(ys), 0), 83);
    int x1 = min(x0 + 1, 83);
    int y1 = min(y0 + 1, 83);
    float Ia = src[y0 * 84 + x0], Ib = src[y1 * 84 + x0];
    float Ic = src[y0 * 84 + x1], Id = src[y1 * 84 + x1];
    float xc = fminf(fmaxf(xs, 0.f), 83.f);
    float yc = fminf(fmaxf(ys, 0.f), 83.f);
    float x0f = (float)x0, x1f = (float)x1, y0f = (float)y0, y1f = (float)y1;
    float o = (x1f - xc) * (y1f - yc) * Ia + (x1f - xc) * (yc - y0f) * Ib +
              (xc - x0f) * (y1f - yc) * Ic + (xc - x0f) * (yc - y0f) * Id;
    outp[(size_t)b * 7056 + p] = o;
}

// ---------------- launch ----------------
extern "C" void kernel_launch(void* const* d_in, const int* in_sizes, int n_in,
                              void* d_out, int out_size) {
    const float* inp = (const float*)d_in[0];
    const float* cw1 = (const float*)d_in[1];
    const float* cb1 = (const float*)d_in[2];
    const float* cw2 = (const float*)d_in[3];
    const float* cb2 = (const float*)d_in[4];
    const float* cw3 = (const float*)d_in[5];
    const float* cb3 = (const float*)d_in[6];
    const float* fcw = (const float*)d_in[7];
    const float* fcb = (const float*)d_in[8];
    const float* otw = (const float*)d_in[9];
    const float* otb = (const float*)d_in[10];
    const float* ctw = (const float*)d_in[11];
    const float* ctb = (const float*)d_in[12];
    const float* m1w = (const float*)d_in[13];
    const float* m1b = (const float*)d_in[14];
    const float* c1w = (const float*)d_in[15];
    const float* c1b = (const float*)d_in[16];
    const float* c2w = (const float*)d_in[17];
    const float* c2b = (const float*)d_in[18];
    const float* c3w = (const float*)d_in[19];
    const float* c3b = (const float*)d_in[20];
    float* outp = (float*)d_out;

    cudaFuncSetAttribute(k_conv1,  cudaFuncAttributeMaxDynamicSharedMemorySize, 72832);
    cudaFuncSetAttribute(k_conv23, cudaFuncAttributeMaxDynamicSharedMemorySize, 168192);
    cudaFuncSetAttribute(k_upconv_hmma4, cudaFuncAttributeMaxDynamicSharedMemorySize, 114912);

    float *p_h3, *p_x, *p_fcpart, *p_m21, *p_m42b, *p_m84b;
    cudaGetSymbolAddress((void**)&p_h3,     g_h3);
    cudaGetSymbolAddress((void**)&p_x,      g_x);
    cudaGetSymbolAddress((void**)&p_fcpart, g_fcpart);
    cudaGetSymbolAddress((void**)&p_m21,    g_m21);
    cudaGetSymbolAddress((void**)&p_m42b,   g_m42b);
    cudaGetSymbolAddress((void**)&p_m84b,   g_m84b);

    // (independent) pack m1 weights into bf16 hi/lo fragments
    k_packW<<<(M1N * 256 + 255) / 256, 256>>>(m1w);
    // encoder
    k_conv1<<<Bsz, 256, 72832>>>(inp, cw1, cb1);
    k_conv23<<<Bsz, 256, 168192>>>(cw2, cb2, cw3, cb3);
    // fc: split-K=7 + fused reduce(relu)+heads
    k_gemm2<<<dim3(EMB / GBN, Bsz / GBM, 7), 256>>>(p_h3, fcw, fcb, p_fcpart,
                                                    Bsz, EMB, 3136, 448, 0);
    k_fcredheads<<<Bsz, 256>>>(fcb, otw, otb, ctw, ctb);
    // pack activations, then m1 GEMM via bf16 3-term HMMA
    k_packA<<<(Bsz * 256 + 255) / 256, 256>>>();
    k_gemmhmma<<<dim3((M1N + 63) / 64, Bsz / 128), 256>>>(m1b, p_m21);
    // decoder: band=8, 512 threads
    k_upconv_hmma4<<<dim3(6, Bsz), 512, 65952>>>(p_m21, c1w, c1b, p_m42b,
                                                 21, 42, 46, 11, 20.f / 41.f,
                                                 5520, 5184);
    k_upconv_hmma4<<<dim3(11, Bsz), 512, 114912>>>(p_m42b, c2w, c2b, p_m84b,
                                                   42, 84, 86, 21, 41.f / 83.f,
                                                   10320, 8064);
    // fused: 1x1 conv + sigmoid masks + flow + warp
    k_final<<<dim3(28, Bsz), 256>>>(inp, c3w, c3b, outp);
    (void)in_sizes; (void)n_in; (void)out_size;
}

// round 17
// speedup vs baseline: 1.8187x; 1.0051x over previous
#include <cuda_runtime.h>
#include <cuda_bf16.h>
#include <math.h>
#include <stdint.h>

#define Bsz 512
#define HH 84
#define WW 84
#define KOBJ 20
#define DEPTH 24
#define EMB 512
#define M1N 10584
#define FCK 3136
#define FCKP (FCK / 2)   /* 1568 pairs */

// ---------------- scratch (static device globals; no allocations) ----------------
__device__ float g_h1[Bsz * 32 * 20 * 20];
__device__ float g_h3[Bsz * 64 * 7 * 7];
__device__ float g_fcpart[7 * Bsz * EMB];
__device__ float g_x [Bsz * EMB];
__device__ float g_ot[Bsz * KOBJ * 2];
__device__ float g_ct[Bsz * 2];
__device__ float g_m21 [Bsz * DEPTH * 21 * 21];
__device__ float g_m42b[Bsz * DEPTH * 42 * 42];
__device__ float g_m84b[Bsz * DEPTH * 84 * 84];
// packed bf16 hi/lo fragment operands
__device__ uint32_t g_m1whi[M1N * 256];
__device__ uint32_t g_m1wlo[M1N * 256];
__device__ uint32_t g_xhi[Bsz * 256];
__device__ uint32_t g_xlo[Bsz * 256];
__device__ uint32_t g_fcwhi[EMB * FCKP];
__device__ uint32_t g_fcwlo[EMB * FCKP];
__device__ uint32_t g_h3hi[Bsz * FCKP];
__device__ uint32_t g_h3lo[Bsz * FCKP];

// ---------------- helpers ----------------
__device__ __forceinline__ uint32_t pack_bf16x2(float lo, float hi) {
    uint32_t r;
    asm("cvt.rn.bf16x2.f32 %0, %1, %2;" : "=r"(r) : "f"(hi), "f"(lo));
    return r;  // low16 = bf16(lo), high16 = bf16(hi)
}
__device__ __forceinline__ void unpack_bf16x2(uint32_t u, float& lo, float& hi) {
    lo = __uint_as_float(u << 16);
    hi = __uint_as_float(u & 0xFFFF0000u);
}
__device__ __forceinline__ float bf16f(float v) {
    return __bfloat162float(__float2bfloat16(v));
}
__device__ __forceinline__ void mma_bf16(float c[4], const uint32_t a[4],
                                         uint32_t b0, uint32_t b1) {
    asm volatile("mma.sync.aligned.m16n8k16.row.col.f32.bf16.bf16.f32 "
        "{%0,%1,%2,%3}, {%4,%5,%6,%7}, {%8,%9}, {%0,%1,%2,%3};"
        : "+f"(c[0]), "+f"(c[1]), "+f"(c[2]), "+f"(c[3])
        : "r"(a[0]), "r"(a[1]), "r"(a[2]), "r"(a[3]), "r"(b0), "r"(b1));
}
__device__ __forceinline__ void mma_bf16_k8(float c[4], uint32_t a0, uint32_t a1,
                                            uint32_t b0) {
    asm volatile("mma.sync.aligned.m16n8k8.row.col.f32.bf16.bf16.f32 "
        "{%0,%1,%2,%3}, {%4,%5}, {%6}, {%0,%1,%2,%3};"
        : "+f"(c[0]), "+f"(c[1]), "+f"(c[2]), "+f"(c[3])
        : "r"(a0), "r"(a1), "r"(b0));
}

// ---------------- generic pack: fp32 rows -> bf16 hi/lo fragment layout ----------
// pair j of row r -> idx r*Kp + (j>>3)*8 + slot(j&7), slot = {0,2,4,6,1,3,5,7}
__global__ __launch_bounds__(256) void k_packAB(const float* __restrict__ src,
                                                uint32_t* __restrict__ dhi,
                                                uint32_t* __restrict__ dlo,
                                                int totalPairs, int Kp) {
    int e = blockIdx.x * 256 + threadIdx.x;
    if (e >= totalPairs) return;
    int r = e / Kp, j = e - r * Kp;
    int s = j >> 3, jj = j & 7;
    int slot = (jj < 4) ? (2 * jj) : (2 * (jj - 4) + 1);
    const float* sp = src + (size_t)r * (2 * Kp) + 2 * j;
    float v0 = sp[0], v1 = sp[1];
    float h0 = bf16f(v0), h1 = bf16f(v1);
    int idx = r * Kp + s * 8 + slot;
    dhi[idx] = pack_bf16x2(h0, h1);
    dlo[idx] = pack_bf16x2(v0 - h0, v1 - h1);
}

// ---------------- fc GEMM via bf16 3-term HMMA, split-K=7 partials -------------
// C_part[z][512,512] = h3[:, z*448:(z+1)*448] @ fcw[:, same]^T
__global__ __launch_bounds__(256) void k_fchmma(float* __restrict__ Cpart) {
    int tid = threadIdx.x, lane = tid & 31, wid = tid >> 5;
    int g = lane >> 2, tg = lane & 3;
    int bn = blockIdx.x * 64, bm = blockIdx.y * 128;
    int z = blockIdx.z;
    int nw = wid & 3, mw = wid >> 2;
    int m0 = bm + mw * 64, n0 = bn + nw * 16;
    const uint2* Ahi = (const uint2*)g_h3hi;
    const uint2* Alo = (const uint2*)g_h3lo;
    const uint2* Whi = (const uint2*)g_fcwhi;
    const uint2* Wlo = (const uint2*)g_fcwlo;
    const int KP2 = FCKP / 2;  // uint2 per row = 784
    float acc[4][2][4];
    #pragma unroll
    for (int t = 0; t < 4; t++)
        #pragma unroll
        for (int u = 0; u < 2; u++)
            #pragma unroll
            for (int q = 0; q < 4; q++) acc[t][u][q] = 0.f;

    int s0 = z * 28;
    #pragma unroll 4
    for (int si = 0; si < 28; si++) {
        int s = s0 + si;
        uint2 wh[2], wl[2];
        #pragma unroll
        for (int u = 0; u < 2; u++) {
            int n = n0 + 8 * u + g;
            wh[u] = Whi[n * KP2 + s * 4 + tg];
            wl[u] = Wlo[n * KP2 + s * 4 + tg];
        }
        #pragma unroll
        for (int t = 0; t < 4; t++) {
            int rA = m0 + 16 * t + g;
            uint2 hA = Ahi[rA * KP2 + s * 4 + tg];
            uint2 hB = Ahi[(rA + 8) * KP2 + s * 4 + tg];
            uint2 lA = Alo[rA * KP2 + s * 4 + tg];
            uint2 lB = Alo[(rA + 8) * KP2 + s * 4 + tg];
            uint32_t ah[4] = {hA.x, hB.x, hA.y, hB.y};
            uint32_t al[4] = {lA.x, lB.x, lA.y, lB.y};
            #pragma unroll
            for (int u = 0; u < 2; u++) {
                mma_bf16(acc[t][u], ah, wh[u].x, wh[u].y);
                mma_bf16(acc[t][u], al, wh[u].x, wh[u].y);
                mma_bf16(acc[t][u], ah, wl[u].x, wl[u].y);
            }
        }
    }
    float* Cp = Cpart + (size_t)z * Bsz * EMB;
    #pragma unroll
    for (int t = 0; t < 4; t++) {
        int row = m0 + 16 * t + g;
        #pragma unroll
        for (int u = 0; u < 2; u++) {
            int c = n0 + 8 * u + 2 * tg;
            Cp[(size_t)row * EMB + c]           = acc[t][u][0];
            Cp[(size_t)row * EMB + c + 1]       = acc[t][u][1];
            Cp[(size_t)(row + 8) * EMB + c]     = acc[t][u][2];
            Cp[(size_t)(row + 8) * EMB + c + 1] = acc[t][u][3];
        }
    }
}

// ---------------- m1 GEMM via bf16 3-term HMMA: C[512,10584] = x @ W^T + b ------
__global__ __launch_bounds__(256) void k_gemmhmma(const float* __restrict__ bias,
                                                  float* __restrict__ C) {
    int tid = threadIdx.x, lane = tid & 31, wid = tid >> 5;
    int g = lane >> 2, tg = lane & 3;
    int bn = blockIdx.x * 64, bm = blockIdx.y * 128;
    int nw = wid & 3, mw = wid >> 2;
    int m0 = bm + mw * 64, n0 = bn + nw * 16;
    const uint2* Ahi = (const uint2*)g_xhi;
    const uint2* Alo = (const uint2*)g_xlo;
    const uint2* Whi = (const uint2*)g_m1whi;
    const uint2* Wlo = (const uint2*)g_m1wlo;
    float acc[4][2][4];
    #pragma unroll
    for (int t = 0; t < 4; t++)
        #pragma unroll
        for (int u = 0; u < 2; u++)
            #pragma unroll
            for (int q = 0; q < 4; q++) acc[t][u][q] = 0.f;

    int nidx[2];
    #pragma unroll
    for (int u = 0; u < 2; u++) {
        int n = n0 + 8 * u + g;
        nidx[u] = (n < M1N) ? n : (M1N - 1);   // clamp (stores guarded)
    }

    #pragma unroll 4
    for (int s = 0; s < 32; s++) {
        uint2 wh[2], wl[2];
        #pragma unroll
        for (int u = 0; u < 2; u++) {
            wh[u] = Whi[nidx[u] * 128 + s * 4 + tg];
            wl[u] = Wlo[nidx[u] * 128 + s * 4 + tg];
        }
        #pragma unroll
        for (int t = 0; t < 4; t++) {
            int rA = m0 + 16 * t + g;
            uint2 hA = Ahi[rA * 128 + s * 4 + tg];
            uint2 hB = Ahi[(rA + 8) * 128 + s * 4 + tg];
            uint2 lA = Alo[rA * 128 + s * 4 + tg];
            uint2 lB = Alo[(rA + 8) * 128 + s * 4 + tg];
            uint32_t ah[4] = {hA.x, hB.x, hA.y, hB.y};
            uint32_t al[4] = {lA.x, lB.x, lA.y, lB.y};
            #pragma unroll
            for (int u = 0; u < 2; u++) {
                mma_bf16(acc[t][u], ah, wh[u].x, wh[u].y);
                mma_bf16(acc[t][u], al, wh[u].x, wh[u].y);
                mma_bf16(acc[t][u], ah, wl[u].x, wl[u].y);
            }
        }
    }

    #pragma unroll
    for (int t = 0; t < 4; t++) {
        int row = m0 + 16 * t + g;
        #pragma unroll
        for (int u = 0; u < 2; u++) {
            int c = n0 + 8 * u + 2 * tg;
            if (c < M1N) {
                float b0 = bias[c], b1 = bias[c + 1];
                C[(size_t)row * M1N + c]           = acc[t][u][0] + b0;
                C[(size_t)row * M1N + c + 1]       = acc[t][u][1] + b1;
                C[(size_t)(row + 8) * M1N + c]     = acc[t][u][2] + b0;
                C[(size_t)(row + 8) * M1N + c + 1] = acc[t][u][3] + b1;
            }
        }
    }
}

// ---------------- conv1: [B,2,84,84] k8 s4 -> [B,32,20,20], relu ----------------
__global__ __launch_bounds__(256) void k_conv1(const float* __restrict__ inp,
                                               const float* __restrict__ w,
                                               const float* __restrict__ bias) {
    extern __shared__ float sm[];
    float* sIn = sm;          // 14112
    float* sW  = sm + 14112;  // 4096
    int b = blockIdx.x, tid = threadIdx.x;
    const float* ip = inp + b * 14112;
    for (int i = tid; i < 14112; i += 256) sIn[i] = ip[i];
    for (int i = tid; i < 4096;  i += 256) sW[i]  = w[i];
    __syncthreads();
    for (int o = tid; o < 3200; o += 256) {
        int oc = o / 100; int r = o % 100;
        int oy = (r / 10) * 2, ox = (r % 10) * 2;
        float a00 = 0.f, a01 = 0.f, a10 = 0.f, a11 = 0.f;
        for (int ic = 0; ic < 2; ic++) {
            const float* wp  = sW + (oc * 2 + ic) * 64;
            const float* inb = sIn + ic * 7056;
            #pragma unroll
            for (int ky = 0; ky < 8; ky++) {
                const float* r0 = inb + (oy * 4 + ky) * 84 + ox * 4;
                const float* r1 = r0 + 4 * 84;
                float v0[12], v1[12];
                #pragma unroll
                for (int j = 0; j < 12; j++) { v0[j] = r0[j]; v1[j] = r1[j]; }
                #pragma unroll
                for (int kx = 0; kx < 8; kx++) {
                    float ww = wp[ky * 8 + kx];
                    a00 += v0[kx] * ww;  a01 += v0[kx + 4] * ww;
                    a10 += v1[kx] * ww;  a11 += v1[kx + 4] * ww;
                }
            }
        }
        float bb = bias[oc];
        float* op = g_h1 + b * 12800 + oc * 400 + oy * 20 + ox;
        op[0]  = fmaxf(a00 + bb, 0.f); op[1]  = fmaxf(a01 + bb, 0.f);
        op[20] = fmaxf(a10 + bb, 0.f); op[21] = fmaxf(a11 + bb, 0.f);
    }
}

// ---------------- conv2+conv3 fused (h2 stays in smem) ----------------
__global__ __launch_bounds__(256) void k_conv23(const float* __restrict__ w2,
                                                const float* __restrict__ b2,
                                                const float* __restrict__ w3,
                                                const float* __restrict__ b3) {
    extern __shared__ float sm[];
    float* sIn1 = sm;
    float* sW2  = sm + 12800;
    float* sH2  = sm + 36864;
    int b = blockIdx.x, tid = threadIdx.x;
    const float* ip = g_h1 + b * 12800;
    for (int i = tid; i < 12800; i += 256) sIn1[i] = ip[i];
    for (int ch = 0; ch < 2; ch++) {
        __syncthreads();
        for (int i = tid; i < 16384; i += 256) sW2[i] = w2[ch * 16384 + i];
        __syncthreads();
        if (tid < 216) {
            int ocg = tid / 27; int r = tid % 27; int oy = r / 3; int oxg = (r % 3) * 3;
            float acc[4][3] = {};
            int iy0 = oy * 2, ix0 = oxg * 2;
            for (int ic = 0; ic < 32; ic++) {
                #pragma unroll
                for (int ky = 0; ky < 4; ky++) {
                    const float* rp = sIn1 + ic * 400 + (iy0 + ky) * 20 + ix0;
                    float v[8];
                    #pragma unroll
                    for (int j = 0; j < 8; j++) v[j] = rp[j];
                    #pragma unroll
                    for (int u = 0; u < 4; u++) {
                        const float* wp = sW2 + ((ocg * 4 + u) * 32 + ic) * 16 + ky * 4;
                        #pragma unroll
                        for (int kx = 0; kx < 4; kx++) {
                            float ww = wp[kx];
                            acc[u][0] += v[kx] * ww;
                            acc[u][1] += v[kx + 2] * ww;
                            acc[u][2] += v[kx + 4] * ww;
                        }
                    }
                }
            }
            #pragma unroll
            for (int u = 0; u < 4; u++) {
                int oc = ch * 32 + ocg * 4 + u;
                float bb = b2[oc];
                float* op = sH2 + oc * 81 + oy * 9 + oxg;
                #pragma unroll
                for (int j = 0; j < 3; j++) op[j] = fmaxf(acc[u][j] + bb, 0.f);
            }
        }
    }
    __syncthreads();
    for (int i = tid; i < 36864; i += 256) sm[i] = w3[i];
    __syncthreads();
    for (int it = tid; it < 448; it += 256) {
        int oc = it / 7, oy = it % 7;
        float acc[7] = {};
        for (int ic = 0; ic < 64; ic++) {
            const float* wp = sm + (oc * 64 + ic) * 9;
            #pragma unroll
            for (int ky = 0; ky < 3; ky++) {
                const float* rp = sH2 + ic * 81 + (oy + ky) * 9;
                float v[9];
                #pragma unroll
                for (int j = 0; j < 9; j++) v[j] = rp[j];
                #pragma unroll
                for (int kx = 0; kx < 3; kx++) {
                    float ww = wp[ky * 3 + kx];
                    #pragma unroll
                    for (int j = 0; j < 7; j++) acc[j] += v[j + kx] * ww;
                }
            }
        }
        float bb = b3[oc];
        float* op = g_h3 + b * 3136 + oc * 49 + oy * 7;
        #pragma unroll
        for (int j = 0; j < 7; j++) op[j] = fmaxf(acc[j] + bb, 0.f);
    }
}

// ---------------- fc reduce + heads + fused g_x fragment pack ----------------
__global__ __launch_bounds__(256) void k_fcredheads(const float* __restrict__ fcb,
                                                    const float* __restrict__ otw,
                                                    const float* __restrict__ otb,
                                                    const float* __restrict__ ctw,
                                                    const float* __restrict__ ctb) {
    __shared__ float sx[EMB];
    int b = blockIdx.x, tid = threadIdx.x;
    int lane = tid & 31, wid = tid >> 5;
    for (int i = tid; i < EMB; i += 256) {
        float s = fcb[i];
        #pragma unroll
        for (int p = 0; p < 7; p++) s += g_fcpart[p * Bsz * EMB + b * EMB + i];
        float v = fmaxf(s, 0.f);
        g_x[b * EMB + i] = v;
        sx[i] = v;
    }
    __syncthreads();
    // pack g_x fragments (256 pairs, one per thread)
    {
        int j = tid;
        int s = j >> 3, jj = j & 7;
        int slot = (jj < 4) ? (2 * jj) : (2 * (jj - 4) + 1);
        float x0 = sx[2 * j], x1 = sx[2 * j + 1];
        float h0 = bf16f(x0), h1 = bf16f(x1);
        int idx = b * 256 + s * 8 + slot;
        g_xhi[idx] = pack_bf16x2(h0, h1);
        g_xlo[idx] = pack_bf16x2(x0 - h0, x1 - h1);
    }
    #pragma unroll
    for (int j = 0; j < 6; j++) {
        int o = j * 8 + wid;
        if (o < 42) {
            const float* wp = (o < 40) ? (otw + o * EMB) : (ctw + (o - 40) * EMB);
            float s = 0.f;
            #pragma unroll
            for (int k = lane; k < EMB; k += 32) s += sx[k] * wp[k];
            #pragma unroll
            for (int d = 16; d > 0; d >>= 1) s += __shfl_xor_sync(0xFFFFFFFFu, s, d);
            if (lane == 0) {
                if (o < 40) g_ot[b * 40 + o] = s + otb[o];
                else        g_ct[b * 2 + (o - 40)] = s + ctb[o - 40];
            }
        }
    }
}

// ==== fused upsample + residual 3x3 conv, bf16 3-term, k16+k8, band=8, 512 thr ====
__global__ __launch_bounds__(512, 1) void k_upconv_hmma4(
        const float* __restrict__ src, const float* __restrict__ w,
        const float* __restrict__ bias, float* __restrict__ out,
        int inS, int S, int Wp, int npx, float scale, int tileU, int auxU) {
    extern __shared__ uint32_t smu[];
    uint32_t* sHi = smu;
    uint32_t* sLo = smu + tileU;
    uint32_t* sAux = smu + 2 * tileU;        // raw staging then B fragments (5184)
    float* sRawF = (float*)sAux;
    float* sBias = (float*)(sAux + auxU);
    int tid = threadIdx.x, lane = tid & 31, wid = tid >> 5;
    int b = blockIdx.y, band = blockIdx.x;
    int y0 = band * 8;
    int g = lane >> 2, tg = lane & 3;

    // phase 0: stage raw src rows [ic][8][inS] + bias
    int sy0 = (int)(fmaxf((float)(y0 - 1), 0.f) * scale);
    const float* srcb = src + (size_t)b * 24 * inS * inS;
    int rawTot = 24 * 8 * inS;
    for (int e = tid; e < rawTot; e += 512) {
        int ic = e / (8 * inS);
        int r2 = e % (8 * inS);
        int ry = r2 / inS, x = r2 % inS;
        int sy = sy0 + ry;
        sRawF[e] = (sy < inS) ? srcb[(size_t)ic * inS * inS + sy * inS + x] : 0.f;
    }
    if (tid < 24) sBias[tid] = bias[tid];
    __syncthreads();

    // phase 1: bilinear upsample -> bf16 hi/lo 12-u32 records (10 tile rows)
    for (int pix = tid; pix < 10 * Wp; pix += 512) {
        int r = pix / Wp, c = pix - r * Wp;
        int gy = y0 + r - 1, gx = c - 1;
        uint32_t* rh = sHi + pix * 12;
        uint32_t* rl = sLo + pix * 12;
        float vb[24];
        if (gy >= 0 && gy < S && gx >= 0 && gx < S) {
            float py = gy * scale;
            int yl = min((int)py, inS - 2);
            float wy = py - (float)yl;
            float px = gx * scale;
            int xl = min((int)px, inS - 2);
            float wx = px - (float)xl;
            const float* base = sRawF + (yl - sy0) * inS + xl;
            #pragma unroll
            for (int ic = 0; ic < 24; ic++) {
                const float* rp = base + ic * (8 * inS);
                float v00 = rp[0], v01 = rp[1], v10 = rp[inS], v11 = rp[inS + 1];
                vb[ic] = (1.f - wy) * ((1.f - wx) * v00 + wx * v01) +
                         wy * ((1.f - wx) * v10 + wx * v11);
            }
        } else {
            #pragma unroll
            for (int ic = 0; ic < 24; ic++) vb[ic] = 0.f;
        }
        const int slotA[12] = {0, 2, 4, 6, 1, 3, 5, 7, 8, 9, 10, 11};
        #pragma unroll
        for (int j = 0; j < 12; j++) {
            uint32_t h = pack_bf16x2(vb[2 * j], vb[2 * j + 1]);
            float h0, h1;
            unpack_bf16x2(h, h0, h1);
            uint32_t l = pack_bf16x2(vb[2 * j] - h0, vb[2 * j + 1] - h1);
            rh[slotA[j]] = h;
            rl[slotA[j]] = l;
        }
    }
    __syncthreads();

    // phase 2: raw dead; build B fragments in sAux (5184 u32; verified layout)
    for (int e = tid; e < 5184; e += 512) {
        int tap = e / 576;
        int r = e % 576;
        int nt, hl, ic0, oc;
        if (r < 384) {
            int rr = r & 1; int q = r >> 1;
            int ln = q & 31; int hn = q >> 5;
            nt = hn % 3; hl = hn / 3;
            oc = nt * 8 + (ln >> 2);
            ic0 = 2 * (ln & 3) + 8 * rr;
        } else {
            int u = r - 384;
            int ln = u & 31; int hn = u >> 5;
            nt = hn % 3; hl = hn / 3;
            oc = nt * 8 + (ln >> 2);
            ic0 = 16 + 2 * (ln & 3);
        }
        float wv0 = w[(oc * 24 + ic0) * 9 + tap];
        float wv1 = w[(oc * 24 + ic0 + 1) * 9 + tap];
        float h0 = bf16f(wv0), h1 = bf16f(wv1);
        float v0 = hl ? (wv0 - h0) : h0;
        float v1 = hl ? (wv1 - h1) : h1;
        smu[2 * tileU + e] = pack_bf16x2(v0, v1);
    }
    __syncthreads();

    // phase 3: k-substep-outer, patch-inner (up to 3 patches per warp, 16 warps)
    const uint2* sHi2 = (const uint2*)sHi;
    const uint2* sLo2 = (const uint2*)sLo;
    int pr = g >> 2;
    int npatch = 2 * npx;
    int pix0[3]; bool pv[3]; int colb_[3]; int rowb_[3];
    #pragma unroll
    for (int pi = 0; pi < 3; pi++) {
        int p = wid + 16 * pi;
        pv[pi] = (p < npatch);
        int pp = pv[pi] ? p : 0;
        int pr2 = pp / npx, pcol = pp % npx;
        colb_[pi] = pcol * 4 + (g & 3);
        rowb_[pi] = pr2 * 4 + pr;
        pix0[pi] = rowb_[pi] * Wp + colb_[pi];
    }
    float acc[3][12];
    #pragma unroll
    for (int pi = 0; pi < 3; pi++)
        #pragma unroll
        for (int q = 0; q < 12; q++) acc[pi][q] = 0.f;

    #pragma unroll
    for (int ky = 0; ky < 3; ky++) {
        #pragma unroll
        for (int kx = 0; kx < 3; kx++) {
            int tap = ky * 3 + kx;
            const uint2* b16 = (const uint2*)(sAux + tap * 576);
            uint2 bh0 = b16[lane],       bh1 = b16[lane + 32],  bh2 = b16[lane + 64];
            uint2 bl0 = b16[lane + 96],  bl1 = b16[lane + 128], bl2 = b16[lane + 160];
            #pragma unroll
            for (int pi = 0; pi < 3; pi++) {
                if (!pv[pi]) continue;
                int pixA = pix0[pi] + ky * Wp + kx;
                int pixB = pixA + 2 * Wp;
                uint2 hA = sHi2[pixA * 6 + tg], hB = sHi2[pixB * 6 + tg];
                uint2 lA = sLo2[pixA * 6 + tg], lB = sLo2[pixB * 6 + tg];
                uint32_t ah[4] = {hA.x, hB.x, hA.y, hB.y};
                uint32_t al[4] = {lA.x, lB.x, lA.y, lB.y};
                mma_bf16(acc[pi] + 0, ah, bh0.x, bh0.y);
                mma_bf16(acc[pi] + 4, ah, bh1.x, bh1.y);
                mma_bf16(acc[pi] + 8, ah, bh2.x, bh2.y);
                mma_bf16(acc[pi] + 0, al, bh0.x, bh0.y);
                mma_bf16(acc[pi] + 4, al, bh1.x, bh1.y);
                mma_bf16(acc[pi] + 8, al, bh2.x, bh2.y);
                mma_bf16(acc[pi] + 0, ah, bl0.x, bl0.y);
                mma_bf16(acc[pi] + 4, ah, bl1.x, bl1.y);
                mma_bf16(acc[pi] + 8, ah, bl2.x, bl2.y);
            }
            const uint32_t* b8 = sAux + tap * 576 + 384;
            uint32_t c8h0 = b8[lane],      c8h1 = b8[lane + 32],  c8h2 = b8[lane + 64];
            uint32_t c8l0 = b8[lane + 96], c8l1 = b8[lane + 128], c8l2 = b8[lane + 160];
            #pragma unroll
            for (int pi = 0; pi < 3; pi++) {
                if (!pv[pi]) continue;
                int pixA = pix0[pi] + ky * Wp + kx;
                int pixB = pixA + 2 * Wp;
                uint32_t a0h = sHi[pixA * 12 + 8 + tg], a1h = sHi[pixB * 12 + 8 + tg];
                uint32_t a0l = sLo[pixA * 12 + 8 + tg], a1l = sLo[pixB * 12 + 8 + tg];
                mma_bf16_k8(acc[pi] + 0, a0h, a1h, c8h0);
                mma_bf16_k8(acc[pi] + 4, a0h, a1h, c8h1);
                mma_bf16_k8(acc[pi] + 8, a0h, a1h, c8h2);
                mma_bf16_k8(acc[pi] + 0, a0l, a1l, c8h0);
                mma_bf16_k8(acc[pi] + 4, a0l, a1l, c8h1);
                mma_bf16_k8(acc[pi] + 8, a0l, a1l, c8h2);
                mma_bf16_k8(acc[pi] + 0, a0h, a1h, c8l0);
                mma_bf16_k8(acc[pi] + 4, a0h, a1h, c8l1);
                mma_bf16_k8(acc[pi] + 8, a0h, a1h, c8l2);
            }
        }
    }

    // epilogue: residual reconstructed hi+lo, + bias, relu, masked stores
    float* ob = out + (size_t)b * 24 * S * S;
    #pragma unroll
    for (int pi = 0; pi < 3; pi++) {
        if (!pv[pi]) continue;
        int colb = colb_[pi];
        int gx = colb;
        int gy0 = y0 + rowb_[pi], gy1 = gy0 + 2;
        bool v0ok = (gy0 < S) && (gx < S);
        bool v1ok = (gy1 < S) && (gx < S);
        const uint32_t* ch0 = sHi + ((rowb_[pi] + 1) * Wp + colb + 1) * 12;
        const uint32_t* cl0 = sLo + ((rowb_[pi] + 1) * Wp + colb + 1) * 12;
        const uint32_t* ch1 = ch0 + 2 * Wp * 12;
        const uint32_t* cl1 = cl0 + 2 * Wp * 12;
        #pragma unroll
        for (int nt = 0; nt < 3; nt++) {
            const float* cp = acc[pi] + nt * 4;
            int oc = nt * 8 + 2 * tg;
            int j = nt * 4 + tg;
            int slot = (j < 8) ? (2 * (j & 3) + (j >> 2)) : j;
            float b0v = sBias[oc], b1v = sBias[oc + 1];
            if (v0ok) {
                float h0, h1, l0, l1;
                unpack_bf16x2(ch0[slot], h0, h1);
                unpack_bf16x2(cl0[slot], l0, l1);
                ob[((size_t)oc * S + gy0) * S + gx] =
                    fmaxf(cp[0] + h0 + l0 + b0v, 0.f);
                ob[((size_t)(oc + 1) * S + gy0) * S + gx] =
                    fmaxf(cp[1] + h1 + l1 + b1v, 0.f);
            }
            if (v1ok) {
                float h0, h1, l0, l1;
                unpack_bf16x2(ch1[slot], h0, h1);
                unpack_bf16x2(cl1[slot], l0, l1);
                ob[((size_t)oc * S + gy1) * S + gx] =
                    fmaxf(cp[2] + h0 + l0 + b0v, 0.f);
                ob[((size_t)(oc + 1) * S + gy1) * S + gx] =
                    fmaxf(cp[3] + h1 + l1 + b1v, 0.f);
            }
        }
    }
}

// ---------------- fused epilogue: 1x1 conv + sigmoid + flow + ct + grid + warp --------
__global__ __launch_bounds__(256) void k_final(const float* __restrict__ inp,
                                               const float* __restrict__ c3w,
                                               const float* __restrict__ c3b,
                                               float* __restrict__ outp) {
    __shared__ float s_w[KOBJ * 24];
    __shared__ float s_b[KOBJ];
    __shared__ float s_ot[KOBJ * 2];
    __shared__ float s_ct[2];
    int b = blockIdx.y, tid = threadIdx.x;
    int p = blockIdx.x * 256 + tid;
    for (int i = tid; i < KOBJ * 24; i += 256) s_w[i] = c3w[i];
    if (tid < KOBJ) s_b[tid] = c3b[tid];
    if (tid < KOBJ * 2) s_ot[tid] = g_ot[b * 40 + tid];
    if (tid < 2) s_ct[tid] = g_ct[b * 2 + tid];
    __syncthreads();
    if (p >= 7056) return;
    const float* mp = g_m84b + (size_t)b * 24 * 7056 + p;
    float mv[24];
    #pragma unroll
    for (int c = 0; c < 24; c++) mv[c] = mp[c * 7056];
    float fy = s_ct[0], fx = s_ct[1];
    #pragma unroll 4
    for (int k = 0; k < KOBJ; k++) {
        float s = s_b[k];
        #pragma unroll
        for (int c = 0; c < 24; c++) s += mv[c] * s_w[k * 24 + c];
        float mask = 1.f / (1.f + __expf(-s));
        fy += mask * s_ot[k * 2];
        fx += mask * s_ot[k * 2 + 1];
    }
    int gy = p / 84, gx = p % 84;
    const float isf = 0.01f * 84.0f;
    float ys = isf * fy + (float)gy;
    float xs = isf * fx + (float)gx;
    const float* src = inp + (size_t)b * 14112 + 7056;
    int x0 = min(max((int)floorf(xs), 0), 83);
    int y0 = min(max((int)floorf(ys), 0), 83);
    int x1 = min(x0 + 1, 83);
    int y1 = min(y0 + 1, 83);
    float Ia = src[y0 * 84 + x0], Ib = src[y1 * 84 + x0];
    float Ic = src[y0 * 84 + x1], Id = src[y1 * 84 + x1];
    float xc = fminf(fmaxf(xs, 0.f), 83.f);
    float yc = fminf(fmaxf(ys, 0.f), 83.f);
    float x0f = (float)x0, x1f = (float)x1, y0f = (float)y0, y1f = (float)y1;
    float o = (x1f - xc) * (y1f - yc) * Ia + (x1f - xc) * (yc - y0f) * Ib +
              (xc - x0f) * (y1f - yc) * Ic + (xc - x0f) * (yc - y0f) * Id;
    outp[(size_t)b * 7056 + p] = o;
}

// ---------------- launch ----------------
extern "C" void kernel_launch(void* const* d_in, const int* in_sizes, int n_in,
                              void* d_out, int out_size) {
    const float* inp = (const float*)d_in[0];
    const float* cw1 = (const float*)d_in[1];
    const float* cb1 = (const float*)d_in[2];
    const float* cw2 = (const float*)d_in[3];
    const float* cb2 = (const float*)d_in[4];
    const float* cw3 = (const float*)d_in[5];
    const float* cb3 = (const float*)d_in[6];
    const float* fcw = (const float*)d_in[7];
    const float* fcb = (const float*)d_in[8];
    const float* otw = (const float*)d_in[9];
    const float* otb = (const float*)d_in[10];
    const float* ctw = (const float*)d_in[11];
    const float* ctb = (const float*)d_in[12];
    const float* m1w = (const float*)d_in[13];
    const float* m1b = (const float*)d_in[14];
    const float* c1w = (const float*)d_in[15];
    const float* c1b = (const float*)d_in[16];
    const float* c2w = (const float*)d_in[17];
    const float* c2b = (const float*)d_in[18];
    const float* c3w = (const float*)d_in[19];
    const float* c3b = (const float*)d_in[20];
    float* outp = (float*)d_out;

    cudaFuncSetAttribute(k_conv1,  cudaFuncAttributeMaxDynamicSharedMemorySize, 72832);
    cudaFuncSetAttribute(k_conv23, cudaFuncAttributeMaxDynamicSharedMemorySize, 168192);
    cudaFuncSetAttribute(k_upconv_hmma4, cudaFuncAttributeMaxDynamicSharedMemorySize, 114912);

    float *p_h3, *p_fcpart, *p_m21, *p_m42b, *p_m84b;
    uint32_t *p_m1whi, *p_m1wlo, *p_fcwhi, *p_fcwlo, *p_h3hi, *p_h3lo;
    cudaGetSymbolAddress((void**)&p_h3,     g_h3);
    cudaGetSymbolAddress((void**)&p_fcpart, g_fcpart);
    cudaGetSymbolAddress((void**)&p_m21,    g_m21);
    cudaGetSymbolAddress((void**)&p_m42b,   g_m42b);
    cudaGetSymbolAddress((void**)&p_m84b,   g_m84b);
    cudaGetSymbolAddress((void**)&p_m1whi,  g_m1whi);
    cudaGetSymbolAddress((void**)&p_m1wlo,  g_m1wlo);
    cudaGetSymbolAddress((void**)&p_fcwhi,  g_fcwhi);
    cudaGetSymbolAddress((void**)&p_fcwlo,  g_fcwlo);
    cudaGetSymbolAddress((void**)&p_h3hi,   g_h3hi);
    cudaGetSymbolAddress((void**)&p_h3lo,   g_h3lo);

    // (independent) pack weights into bf16 hi/lo fragments
    k_packAB<<<(M1N * 256 + 255) / 256, 256>>>(m1w, p_m1whi, p_m1wlo, M1N * 256, 256);
    k_packAB<<<(EMB * FCKP + 255) / 256, 256>>>(fcw, p_fcwhi, p_fcwlo, EMB * FCKP, FCKP);
    // encoder
    k_conv1<<<Bsz, 256, 72832>>>(inp, cw1, cb1);
    k_conv23<<<Bsz, 256, 168192>>>(cw2, cb2, cw3, cb3);
    // pack h3, then fc via bf16 3-term HMMA split-K=7 + fused reduce+heads+packA
    k_packAB<<<(Bsz * FCKP + 255) / 256, 256>>>(p_h3, p_h3hi, p_h3lo, Bsz * FCKP, FCKP);
    k_fchmma<<<dim3(EMB / 64, Bsz / 128, 7), 256>>>(p_fcpart);
    k_fcredheads<<<Bsz, 256>>>(fcb, otw, otb, ctw, ctb);
    // m1 GEMM via bf16 3-term HMMA
    k_gemmhmma<<<dim3((M1N + 63) / 64, Bsz / 128), 256>>>(m1b, p_m21);
    // decoder: band=8, 512 threads
    k_upconv_hmma4<<<dim3(6, Bsz), 512, 65952>>>(p_m21, c1w, c1b, p_m42b,
                                                 21, 42, 46, 11, 20.f / 41.f,
                                                 5520, 5184);
    k_upconv_hmma4<<<dim3(11, Bsz), 512, 114912>>>(p_m42b, c2w, c2b, p_m84b,
                                                   42, 84, 86, 21, 41.f / 83.f,
                                                   10320, 8064);
    // fused: 1x1 conv + sigmoid masks + flow + warp
    k_final<<<dim3(28, Bsz), 256>>>(inp, c3w, c3b, outp);
    (void)in_sizes; (void)n_in; (void)out_size;
}